// round 11
// baseline (speedup 1.0000x reference)
#include <cuda_runtime.h>
#include <cuda_bf16.h>
#include <math.h>
#include <stdint.h>

#define BB 32
#define TT 2048
#define HH 512

#define MT  64                  // t-rows per CTA
#define KC  64                  // K-chunk
#define NOCH 2                  // N chunks of 128 per CTA (half of total)
#define NC  (NOCH * (HH / KC))  // 16 chunks per CTA

// ---------------- scratch (device globals; no allocation allowed) ----------
__device__ float g_q[BB * HH];
__device__ float g_p[BB * TT];
__device__ float g_scr[BB * TT];    // raw score accumulator (pre-sigmoid)
__device__ float g_ctx[BB * HH];
__device__ float g_sum[BB];
__device__ __nv_bfloat16 g_bwhi[HH * HH];
__device__ __nv_bfloat16 g_bwlo[HH * HH];

// ---------------- SMEM layout (byte offsets from 1024-aligned base) --------
// buffer: [A 16K raw fp32 -> converted hi/lo bf16 in place][BH 16K][BL 16K]
#define OFF_A    0
#define OFF_BH   16384
#define OFF_BL   32768
#define BUF_SZ   49152
#define OFF_QB   98304
#define OFF_W0   100352
#define OFF_W1   102400
#define OFF_W2   104448
#define OFF_SW   106496
#define OFF_LA   108544    // 66 floats
#define SMEM_END 109056
#define SMEM_REQ (SMEM_END + 1024)   // x2 CTAs <= 227KB

// ---------------- helpers ---------------------------------------------------
__device__ __forceinline__ uint32_t smem_u32(const void* p) {
    uint32_t a;
    asm("{ .reg .u64 t; cvta.to.shared.u64 t, %1; cvt.u32.u64 %0, t; }"
        : "=r"(a) : "l"(p));
    return a;
}
__device__ __forceinline__ uint64_t gaddr(const void* p) {
    uint64_t a;
    asm("cvta.to.global.u64 %0, %1;" : "=l"(a) : "l"(p));
    return a;
}
__device__ __forceinline__ void cpa16(uint32_t d, uint64_t s) {
    asm volatile("cp.async.cg.shared.global [%0], [%1], 16;"
                 :: "r"(d), "l"(s) : "memory");
}
#define CP_COMMIT() asm volatile("cp.async.commit_group;" ::: "memory")
#define CP_WAIT0()  asm volatile("cp.async.wait_group 0;" ::: "memory")

__device__ __forceinline__ void ldsm4(uint32_t* r, uint32_t a) {
    asm volatile("ldmatrix.sync.aligned.m8n8.x4.shared.b16 {%0,%1,%2,%3}, [%4];"
                 : "=r"(r[0]), "=r"(r[1]), "=r"(r[2]), "=r"(r[3]) : "r"(a));
}
__device__ __forceinline__ void mma16816(float* d, const uint32_t* a,
                                         const uint32_t* b) {
    asm volatile(
        "mma.sync.aligned.m16n8k16.row.col.f32.bf16.bf16.f32 "
        "{%0,%1,%2,%3},{%4,%5,%6,%7},{%8,%9},{%0,%1,%2,%3};"
        : "+f"(d[0]), "+f"(d[1]), "+f"(d[2]), "+f"(d[3])
        : "r"(a[0]), "r"(a[1]), "r"(a[2]), "r"(a[3]), "r"(b[0]), "r"(b[1]));
}
__device__ __forceinline__ float ftanh(float x) {
    float y;
    asm("tanh.approx.f32 %0, %1;" : "=f"(y) : "f"(x));
    return y;
}
__device__ __forceinline__ uint32_t pkbf(float a, float b) {
    return ((uint32_t)__bfloat16_as_ushort(__float2bfloat16(b)) << 16)
         |  (uint32_t)__bfloat16_as_ushort(__float2bfloat16(a));
}
// packed pair [bf16(b)|bf16(a)] in one cvt
__device__ __forceinline__ uint32_t bfx2(float a, float b) {
    uint32_t r;
    asm("cvt.rn.bf16x2.f32 %0, %1, %2;" : "=r"(r) : "f"(b), "f"(a));
    return r;
}
// residual pair vs packed hi
__device__ __forceinline__ uint32_t bfx2lo(float a, float b, uint32_t p) {
    float ra = a - __uint_as_float(p << 16);
    float rb = b - __uint_as_float(p & 0xFFFF0000u);
    return bfx2(ra, rb);
}

// ---------------- init: zero scratch + split v_w ----------------------------
__global__ void k_init(const float* __restrict__ v_w) {
    int i = blockIdx.x * 256 + threadIdx.x;
    if (i < BB * HH) g_ctx[i] = 0.f;
    if (i < BB)      g_sum[i] = 0.f;
    if (i < BB * TT) g_scr[i] = 0.f;
    if (i < HH * HH) {
        float x = v_w[i];
        __nv_bfloat16 h = __float2bfloat16(x);
        g_bwhi[i] = h;
        g_bwlo[i] = __float2bfloat16(x - __bfloat162float(h));
    }
}

// q[b,o]: one block per o; warp w covers b in [4w, 4w+4)
__global__ void __launch_bounds__(256)
k_qproj(const float* __restrict__ query, const float* __restrict__ q_w) {
    int o = blockIdx.x, lane = threadIdx.x & 31, warp = threadIdx.x >> 5;
    const float* wrow = q_w + o * HH;
    float acc0 = 0.f, acc1 = 0.f, acc2 = 0.f, acc3 = 0.f;
    int b0 = warp * 4;
    for (int k = lane; k < HH; k += 32) {
        float w = __ldg(wrow + k);
        acc0 += w * __ldg(query + (b0 + 0) * HH + k);
        acc1 += w * __ldg(query + (b0 + 1) * HH + k);
        acc2 += w * __ldg(query + (b0 + 2) * HH + k);
        acc3 += w * __ldg(query + (b0 + 3) * HH + k);
    }
    #pragma unroll
    for (int off = 16; off; off >>= 1) {
        acc0 += __shfl_xor_sync(0xffffffffu, acc0, off);
        acc1 += __shfl_xor_sync(0xffffffffu, acc1, off);
        acc2 += __shfl_xor_sync(0xffffffffu, acc2, off);
        acc3 += __shfl_xor_sync(0xffffffffu, acc3, off);
    }
    if (lane == 0) {
        g_q[(b0 + 0) * HH + o] = acc0;
        g_q[(b0 + 1) * HH + o] = acc1;
        g_q[(b0 + 2) * HH + o] = acc2;
        g_q[(b0 + 3) * HH + o] = acc3;
    }
}

// ---------------- main HMMA kernel ------------------------------------------
// CTA = (b, t-tile of 64, N-half of 256). grid (64, 32): x = t-tile*2 + nh.
// A loaded as raw fp32, split to bf16 hi/lo in-place in smem.
__global__ void __launch_bounds__(256, 2)
k_main(const float* __restrict__ value, const float* __restrict__ la,
       const float* __restrict__ conv_w, const float* __restrict__ conv_b,
       const float* __restrict__ s_w,    const float* __restrict__ bias)
{
    extern __shared__ char smraw[];
    uint32_t raw = smem_u32(smraw);
    uint32_t sb  = (raw + 1023) & ~1023u;
    char* base   = smraw + (sb - raw);

    int tid = threadIdx.x, L = tid & 31, wid = tid >> 5;
    int warp_m = wid >> 2, warp_n = wid & 3;      // 2 x 4
    int b  = blockIdx.y;
    int t0 = (blockIdx.x >> 1) * MT;
    int ochb = (blockIdx.x & 1) * NOCH;           // global o-chunk base (0 or 2)

    uint64_t valG = gaddr(value) + (uint64_t)(((long)b * TT + t0) * HH) * 4;
    uint64_t bwhG = gaddr(g_bwhi);
    uint64_t bwlG = gaddr(g_bwlo);

    // per chunk: A 64x16 fp32 16B-units (1024) + B 2x1024 = 3072; 12/thread
    auto issue_chunk = [&](int pc) {
        int och = ochb + (pc >> 3), kc = pc & 7;
        int kt = kc * KC, o0 = och * 128;
        uint32_t tb = sb + (uint32_t)(pc & 1) * BUF_SZ;
        #pragma unroll
        for (int i = 0; i < 12; i++) {
            int id = tid + i * 256;
            if (id < 1024) {               // A raw fp32: row pitch 256B
                int r = id >> 4, u = id & 15;
                uint32_t so = (uint32_t)(r * 256 + ((u * 16) ^ ((r & 7) << 4)));
                uint64_t ga = ((uint64_t)((long)r * HH + kt) + (uint64_t)(u * 4)) * 4;
                cpa16(tb + OFF_A + so, valG + ga);
            } else {                       // B tiles (hi then lo)
                int id2 = id - 1024;
                int m = id2 >> 10, r = (id2 >> 3) & 127, c8 = id2 & 7;
                uint32_t so = (uint32_t)(r * 128 + ((c8 * 16) ^ ((r & 7) << 4)));
                uint64_t gb = (uint64_t)((long)(o0 + r) * HH + kt + c8 * 8) * 2;
                cpa16(tb + OFF_BL * m + OFF_BH * (1 - m) + so, (m ? bwlG : bwhG) + gb);
            }
        }
    };

    issue_chunk(0);
    CP_COMMIT();

    float* qbF = (float*)(base + OFF_QB);
    float* w0F = (float*)(base + OFF_W0);
    float* w1F = (float*)(base + OFF_W1);
    float* w2F = (float*)(base + OFF_W2);
    float* swF = (float*)(base + OFF_SW);
    float* laF = (float*)(base + OFF_LA);
    for (int i = tid; i < HH; i += 256) {
        qbF[i] = g_q[b * HH + i] + bias[i] + conv_b[i];
        w0F[i] = conv_w[i * 3 + 0];
        w1F[i] = conv_w[i * 3 + 1];
        w2F[i] = conv_w[i * 3 + 2];
        swF[i] = s_w[i];
    }
    if (tid < MT + 2) {
        int gt = t0 - 1 + tid;
        laF[tid] = (gt >= 0 && gt < TT) ? la[b * TT + gt] : 0.f;
    }

    // each warp: 32 rows (2 x m16), 32 cols (4 x n8)
    // A layout: row pitch 256B; hi bf16 in first 128B, lo in second 128B
    uint32_t aRow  = (uint32_t)(warp_m * 32 + (L & 15)) * 256;
    uint32_t bRow  = (uint32_t)(warp_n * 32 + (L & 7) + ((L >> 4) << 3)) * 128;
    uint32_t amask = (uint32_t)(L & 7) << 4;
    uint32_t aColK[4], bColK[4];
    #pragma unroll
    for (int kk = 0; kk < 4; kk++) {
        aColK[kk] = (uint32_t)(kk * 32 + ((L >> 4) << 4)) ^ amask;
        bColK[kk] = (uint32_t)(kk * 32 + (((L >> 3) & 1) << 4)) ^ amask;
    }

    // conversion constants: thread owns row rr, floats jj*16..jj*16+15
    int rr = tid >> 2, jj = tid & 3;
    uint32_t cswz = (uint32_t)(rr & 7) << 4;
    uint32_t crow = (uint32_t)rr * 256;

    float scp[2][2];
    scp[0][0] = scp[0][1] = scp[1][0] = scp[1][1] = 0.f;

    int pc = 0;
    for (int och = 0; och < NOCH; och++) {
        float acc[2][4][4];
        #pragma unroll
        for (int mi = 0; mi < 2; mi++)
            #pragma unroll
            for (int ni = 0; ni < 4; ni++)
                #pragma unroll
                for (int q = 0; q < 4; q++) acc[mi][ni][q] = 0.f;

        for (int kc = 0; kc < 8; kc++, pc++) {
            CP_WAIT0();
            __syncthreads();
            if (pc + 1 < NC) { issue_chunk(pc + 1); CP_COMMIT(); }

            // in-place fp32 -> bf16 hi/lo conversion of this chunk's A.
            // Same-row threads are in the same warp: program order makes all
            // LDS precede all STS for the bytes they share.
            {
                char* rowp = base + OFF_A + (pc & 1) * BUF_SZ + crow;
                float4 f0 = *(float4*)(rowp + (((jj * 4 + 0) * 16) ^ cswz));
                float4 f1 = *(float4*)(rowp + (((jj * 4 + 1) * 16) ^ cswz));
                float4 f2 = *(float4*)(rowp + (((jj * 4 + 2) * 16) ^ cswz));
                float4 f3 = *(float4*)(rowp + (((jj * 4 + 3) * 16) ^ cswz));
                uint4 H0, H1, L0, L1;
                H0.x = bfx2(f0.x, f0.y); H0.y = bfx2(f0.z, f0.w);
                H0.z = bfx2(f1.x, f1.y); H0.w = bfx2(f1.z, f1.w);
                H1.x = bfx2(f2.x, f2.y); H1.y = bfx2(f2.z, f2.w);
                H1.z = bfx2(f3.x, f3.y); H1.w = bfx2(f3.z, f3.w);
                L0.x = bfx2lo(f0.x, f0.y, H0.x); L0.y = bfx2lo(f0.z, f0.w, H0.y);
                L0.z = bfx2lo(f1.x, f1.y, H0.z); L0.w = bfx2lo(f1.z, f1.w, H0.w);
                L1.x = bfx2lo(f2.x, f2.y, H1.x); L1.y = bfx2lo(f2.z, f2.w, H1.y);
                L1.z = bfx2lo(f3.x, f3.y, H1.z); L1.w = bfx2lo(f3.z, f3.w, H1.w);
                uint32_t h0 = ((uint32_t)(2 * jj) * 16) ^ cswz;
                uint32_t h1 = ((uint32_t)(2 * jj + 1) * 16) ^ cswz;
                *(uint4*)(rowp + h0) = H0;
                *(uint4*)(rowp + h1) = H1;
                *(uint4*)(rowp + 128 + h0) = L0;
                *(uint4*)(rowp + 128 + h1) = L1;
            }
            __syncthreads();

            uint32_t tb = sb + (uint32_t)(pc & 1) * BUF_SZ;
            uint32_t aH = tb + OFF_A + aRow;
            uint32_t aL = aH + 128;
            uint32_t bH = tb + OFF_BH + bRow;
            uint32_t bL = tb + OFF_BL + bRow;

            #pragma unroll
            for (int kk = 0; kk < 4; kk++) {
                uint32_t ah[2][4], al[2][4], bh[4][2], bl[4][2];
                #pragma unroll
                for (int mi = 0; mi < 2; mi++) {
                    ldsm4(ah[mi], aH + (uint32_t)(mi * 4096) + aColK[kk]);
                    ldsm4(al[mi], aL + (uint32_t)(mi * 4096) + aColK[kk]);
                }
                #pragma unroll
                for (int n2 = 0; n2 < 2; n2++) {
                    uint32_t rh[4], rl[4];
                    ldsm4(rh, bH + (uint32_t)(n2 * 2048) + bColK[kk]);
                    ldsm4(rl, bL + (uint32_t)(n2 * 2048) + bColK[kk]);
                    bh[2*n2][0] = rh[0]; bh[2*n2][1] = rh[1];
                    bh[2*n2+1][0] = rh[2]; bh[2*n2+1][1] = rh[3];
                    bl[2*n2][0] = rl[0]; bl[2*n2][1] = rl[1];
                    bl[2*n2+1][0] = rl[2]; bl[2*n2+1][1] = rl[3];
                }
                #pragma unroll
                for (int mi = 0; mi < 2; mi++)
                    #pragma unroll
                    for (int ni = 0; ni < 4; ni++) {
                        mma16816(acc[mi][ni], ah[mi], bh[ni]);
                        mma16816(acc[mi][ni], ah[mi], bl[ni]);
                        mma16816(acc[mi][ni], al[mi], bh[ni]);
                    }
            }
        }

        int o0 = (ochb + och) * 128;
        #pragma unroll
        for (int mi = 0; mi < 2; mi++) {
            int r0 = warp_m * 32 + mi * 16 + (L >> 2);
            float la0 = laF[r0],     la1 = laF[r0 + 1], la2 = laF[r0 + 2];
            float lb0 = laF[r0 + 8], lb1 = laF[r0 + 9], lb2 = laF[r0 + 10];
            #pragma unroll
            for (int ni = 0; ni < 4; ni++) {
                int c0 = o0 + warp_n * 32 + ni * 8 + (L & 3) * 2;
                float2 qb = *(const float2*)(qbF + c0);
                float2 w0 = *(const float2*)(w0F + c0);
                float2 w1 = *(const float2*)(w1F + c0);
                float2 w2 = *(const float2*)(w2F + c0);
                float2 sw = *(const float2*)(swF + c0);
                float cva0 = w0.x * la0 + w1.x * la1 + w2.x * la2 + qb.x;
                float cva1 = w0.y * la0 + w1.y * la1 + w2.y * la2 + qb.y;
                float cvb0 = w0.x * lb0 + w1.x * lb1 + w2.x * lb2 + qb.x;
                float cvb1 = w0.y * lb0 + w1.y * lb1 + w2.y * lb2 + qb.y;
                scp[mi][0] += sw.x * ftanh(acc[mi][ni][0] + cva0)
                            + sw.y * ftanh(acc[mi][ni][1] + cva1);
                scp[mi][1] += sw.x * ftanh(acc[mi][ni][2] + cvb0)
                            + sw.y * ftanh(acc[mi][ni][3] + cvb1);
            }
        }
    }

    // partial score for 256 columns -> global accumulator
    #pragma unroll
    for (int mi = 0; mi < 2; mi++)
        #pragma unroll
        for (int h = 0; h < 2; h++) {
            float v = scp[mi][h];
            v += __shfl_xor_sync(0xffffffffu, v, 1);
            v += __shfl_xor_sync(0xffffffffu, v, 2);
            if ((L & 3) == 0) {
                int r = warp_m * 32 + mi * 16 + (L >> 2) + h * 8;
                atomicAdd(&g_scr[b * TT + t0 + r], v);
            }
        }
}

// ---------------- sigmoid + per-batch sum -----------------------------------
__global__ void __launch_bounds__(256)
k_sig(const float* __restrict__ s_b) {
    int i = blockIdx.x * 256 + threadIdx.x;        // 65536 elems
    float p = __fdividef(1.f, 1.f + __expf(-(g_scr[i] + s_b[0])));
    g_p[i] = p;
    #pragma unroll
    for (int off = 16; off; off >>= 1)
        p += __shfl_xor_sync(0xffffffffu, p, off);
    if ((threadIdx.x & 31) == 0) atomicAdd(&g_sum[i >> 11], p);
}

// ---------------- context: g_ctx[b,h] += sum_t p[b,t]*value[b,t,h] ----------
__global__ void __launch_bounds__(256)
k_ctx(const float* __restrict__ value) {
    int b = blockIdx.x, ts = blockIdx.y;
    int h2 = threadIdx.x;                       // float2 column index (0..255)
    const float2* vb = (const float2*)value + ((long)b * TT + ts * 256) * 256 + h2;
    const float* pb  = g_p + b * TT + ts * 256;
    float2 a0 = {0.f, 0.f}, a1 = {0.f, 0.f}, a2 = {0.f, 0.f}, a3 = {0.f, 0.f};
    #pragma unroll 4
    for (int t = 0; t < 256; t += 4) {
        float p0 = pb[t], p1 = pb[t + 1], p2 = pb[t + 2], p3 = pb[t + 3];
        float2 v0 = vb[(long)(t + 0) * 256];
        float2 v1 = vb[(long)(t + 1) * 256];
        float2 v2 = vb[(long)(t + 2) * 256];
        float2 v3 = vb[(long)(t + 3) * 256];
        a0.x += p0 * v0.x; a0.y += p0 * v0.y;
        a1.x += p1 * v1.x; a1.y += p1 * v1.y;
        a2.x += p2 * v2.x; a2.y += p2 * v2.y;
        a3.x += p3 * v3.x; a3.y += p3 * v3.y;
    }
    float rx = (a0.x + a1.x) + (a2.x + a3.x);
    float ry = (a0.y + a1.y) + (a2.y + a3.y);
    atomicAdd(&g_ctx[b * HH + 2 * h2 + 0], rx);
    atomicAdd(&g_ctx[b * HH + 2 * h2 + 1], ry);
}

__global__ void k_fin(float* __restrict__ out) {
    int i = blockIdx.x * 256 + threadIdx.x;
    if (i < BB * HH) out[i] = g_ctx[i] / g_sum[i / HH];
    if (i < BB * TT) out[BB * HH + i] = g_p[i] / g_sum[i / TT];
}

// ---------------------------------------------------------------------------
extern "C" void kernel_launch(void* const* d_in, const int* in_sizes, int n_in,
                              void* d_out, int out_size) {
    const float* query  = (const float*)d_in[0];
    const float* value  = (const float*)d_in[1];
    const float* la     = (const float*)d_in[2];
    const float* conv_w = (const float*)d_in[3];
    const float* conv_b = (const float*)d_in[4];
    const float* q_w    = (const float*)d_in[5];
    const float* v_w    = (const float*)d_in[6];
    const float* s_w    = (const float*)d_in[7];
    const float* s_b    = (const float*)d_in[8];
    const float* bias   = (const float*)d_in[9];
    float* out = (float*)d_out;

    cudaFuncSetAttribute(k_main, cudaFuncAttributeMaxDynamicSharedMemorySize,
                         SMEM_REQ);

    k_init<<<(HH * HH + 255) / 256, 256>>>(v_w);
    k_qproj<<<HH, 256>>>(query, q_w);
    k_main<<<dim3((TT / MT) * 2, BB), 256, SMEM_REQ>>>(value, la, conv_w,
                                                       conv_b, s_w, bias);
    k_sig<<<BB * TT / 256, 256>>>(s_b);
    k_ctx<<<dim3(BB, 8), 256>>>(value);
    k_fin<<<(BB * TT + 255) / 256, 256>>>(out);
}

// round 12
// speedup vs baseline: 1.1418x; 1.1418x over previous
#include <cuda_runtime.h>
#include <cuda_bf16.h>
#include <math.h>
#include <stdint.h>

#define BB 32
#define TT 2048
#define HH 512

#define MT  64                  // t-rows per CTA
#define KC  64                  // K-chunk (fp32 elements)
#define NOCH 2                  // N chunks of 128 per CTA (half of total)
#define NC  (NOCH * (HH / KC))  // 16 chunks per CTA

// ---------------- scratch (device globals; no allocation allowed) ----------
__device__ float g_q[BB * HH];
__device__ float g_p[BB * TT];
__device__ float g_scr[BB * TT];    // raw score accumulator (pre-sigmoid)
__device__ float g_ctx[BB * HH];
__device__ float g_sum[BB];

// ---------------- SMEM layout (byte offsets from 1024-aligned base) --------
// buffer: [A 16K fp32 64x64][B 32K fp32 128x64] ; rows 256B pitch, swizzled
#define OFF_A    0
#define OFF_B    16384
#define BUF_SZ   49152
#define OFF_QB   98304
#define OFF_W0   100352
#define OFF_W1   102400
#define OFF_W2   104448
#define OFF_SW   106496
#define OFF_LA   108544    // 66 floats
#define SMEM_END 109056
#define SMEM_REQ (SMEM_END + 1024)   // x2 CTAs <= 227KB

// ---------------- helpers ---------------------------------------------------
__device__ __forceinline__ uint32_t smem_u32(const void* p) {
    uint32_t a;
    asm("{ .reg .u64 t; cvta.to.shared.u64 t, %1; cvt.u32.u64 %0, t; }"
        : "=r"(a) : "l"(p));
    return a;
}
__device__ __forceinline__ uint64_t gaddr(const void* p) {
    uint64_t a;
    asm("cvta.to.global.u64 %0, %1;" : "=l"(a) : "l"(p));
    return a;
}
__device__ __forceinline__ void cpa16(uint32_t d, uint64_t s) {
    asm volatile("cp.async.cg.shared.global [%0], [%1], 16;"
                 :: "r"(d), "l"(s) : "memory");
}
#define CP_COMMIT() asm volatile("cp.async.commit_group;" ::: "memory")
#define CP_WAIT0()  asm volatile("cp.async.wait_group 0;" ::: "memory")

__device__ __forceinline__ void ldsm4(uint32_t* r, uint32_t a) {
    asm volatile("ldmatrix.sync.aligned.m8n8.x4.shared.b16 {%0,%1,%2,%3}, [%4];"
                 : "=r"(r[0]), "=r"(r[1]), "=r"(r[2]), "=r"(r[3]) : "r"(a));
}
__device__ __forceinline__ void mma_tf32(float* d, const uint32_t* a,
                                         uint32_t b0, uint32_t b1) {
    asm volatile(
        "mma.sync.aligned.m16n8k8.row.col.f32.tf32.tf32.f32 "
        "{%0,%1,%2,%3},{%4,%5,%6,%7},{%8,%9},{%0,%1,%2,%3};"
        : "+f"(d[0]), "+f"(d[1]), "+f"(d[2]), "+f"(d[3])
        : "r"(a[0]), "r"(a[1]), "r"(a[2]), "r"(a[3]), "r"(b0), "r"(b1));
}
__device__ __forceinline__ uint32_t tf32r(uint32_t x) {
    uint32_t y;
    asm("cvt.rna.tf32.f32 %0, %1;" : "=r"(y) : "f"(__uint_as_float(x)));
    return y;
}
__device__ __forceinline__ float ftanh(float x) {
    float y;
    asm("tanh.approx.f32 %0, %1;" : "=f"(y) : "f"(x));
    return y;
}

// ---------------- init: zero accumulators -----------------------------------
__global__ void k_init() {
    int i = blockIdx.x * 256 + threadIdx.x;
    if (i < BB * HH) g_ctx[i] = 0.f;
    if (i < BB)      g_sum[i] = 0.f;
    if (i < BB * TT) g_scr[i] = 0.f;
}

// q[b,o]: one block per o; warp w covers b in [4w, 4w+4)
__global__ void __launch_bounds__(256)
k_qproj(const float* __restrict__ query, const float* __restrict__ q_w) {
    int o = blockIdx.x, lane = threadIdx.x & 31, warp = threadIdx.x >> 5;
    const float* wrow = q_w + o * HH;
    float acc0 = 0.f, acc1 = 0.f, acc2 = 0.f, acc3 = 0.f;
    int b0 = warp * 4;
    for (int k = lane; k < HH; k += 32) {
        float w = __ldg(wrow + k);
        acc0 += w * __ldg(query + (b0 + 0) * HH + k);
        acc1 += w * __ldg(query + (b0 + 1) * HH + k);
        acc2 += w * __ldg(query + (b0 + 2) * HH + k);
        acc3 += w * __ldg(query + (b0 + 3) * HH + k);
    }
    #pragma unroll
    for (int off = 16; off; off >>= 1) {
        acc0 += __shfl_xor_sync(0xffffffffu, acc0, off);
        acc1 += __shfl_xor_sync(0xffffffffu, acc1, off);
        acc2 += __shfl_xor_sync(0xffffffffu, acc2, off);
        acc3 += __shfl_xor_sync(0xffffffffu, acc3, off);
    }
    if (lane == 0) {
        g_q[(b0 + 0) * HH + o] = acc0;
        g_q[(b0 + 1) * HH + o] = acc1;
        g_q[(b0 + 2) * HH + o] = acc2;
        g_q[(b0 + 3) * HH + o] = acc3;
    }
}

// ---------------- main TF32 MMA kernel --------------------------------------
// CTA = (b, t-tile of 64, N-half of 256). grid (64, 32): x = t-tile*2 + nh.
// A = raw value fp32; B = raw v_w fp32; tf32 conversion in registers.
__global__ void __launch_bounds__(256, 2)
k_main(const float* __restrict__ value, const float* __restrict__ v_w,
       const float* __restrict__ la,
       const float* __restrict__ conv_w, const float* __restrict__ conv_b,
       const float* __restrict__ s_w,    const float* __restrict__ bias)
{
    extern __shared__ char smraw[];
    uint32_t raw = smem_u32(smraw);
    uint32_t sb  = (raw + 1023) & ~1023u;
    char* base   = smraw + (sb - raw);

    int tid = threadIdx.x, L = tid & 31, wid = tid >> 5;
    int warp_m = wid >> 2, warp_n = wid & 3;      // 2 x 4
    int b  = blockIdx.y;
    int t0 = (blockIdx.x >> 1) * MT;
    int ochb = (blockIdx.x & 1) * NOCH;           // global o-chunk base (0 or 2)

    uint64_t valG = gaddr(value) + (uint64_t)(((long)b * TT + t0) * HH) * 4;
    uint64_t vwG  = gaddr(v_w);

    // per chunk: A 64x16 units (1024) + B 128x16 units (2048) = 3072; 12/thread
    auto issue_chunk = [&](int pc) {
        int och = ochb + (pc >> 3), kc = pc & 7;
        int kt = kc * KC, o0 = och * 128;
        uint32_t tb = sb + (uint32_t)(pc & 1) * BUF_SZ;
        #pragma unroll
        for (int i = 0; i < 12; i++) {
            int id = tid + i * 256;
            if (id < 1024) {               // A fp32: row pitch 256B
                int r = id >> 4, u = id & 15;
                uint32_t so = (uint32_t)(r * 256 + ((u * 16) ^ ((r & 7) << 4)));
                uint64_t ga = (uint64_t)((long)r * HH + kt + u * 4) * 4;
                cpa16(tb + OFF_A + so, valG + ga);
            } else {                       // B fp32: row pitch 256B
                int id2 = id - 1024;
                int r = id2 >> 4, u = id2 & 15;
                uint32_t so = (uint32_t)(r * 256 + ((u * 16) ^ ((r & 7) << 4)));
                uint64_t gb = (uint64_t)((long)(o0 + r) * HH + kt + u * 4) * 4;
                cpa16(tb + OFF_B + so, vwG + gb);
            }
        }
    };

    issue_chunk(0);
    CP_COMMIT();

    float* qbF = (float*)(base + OFF_QB);
    float* w0F = (float*)(base + OFF_W0);
    float* w1F = (float*)(base + OFF_W1);
    float* w2F = (float*)(base + OFF_W2);
    float* swF = (float*)(base + OFF_SW);
    float* laF = (float*)(base + OFF_LA);
    for (int i = tid; i < HH; i += 256) {
        qbF[i] = g_q[b * HH + i] + bias[i] + conv_b[i];
        w0F[i] = conv_w[i * 3 + 0];
        w1F[i] = conv_w[i * 3 + 1];
        w2F[i] = conv_w[i * 3 + 2];
        swF[i] = s_w[i];
    }
    if (tid < MT + 2) {
        int gt = t0 - 1 + tid;
        laF[tid] = (gt >= 0 && gt < TT) ? la[b * TT + gt] : 0.f;
    }

    // ldmatrix lane constants (shared form for A and B):
    // laneRow = (L&7) + ((L>>3)&1)*8 ; colSel = L>>4 ; swz mask = (L&7)<<4
    uint32_t laneRow = (uint32_t)((L & 7) + ((L >> 3) & 1) * 8);
    uint32_t colSel  = (uint32_t)(L >> 4);
    uint32_t mask    = (uint32_t)(L & 7) << 4;
    uint32_t aOff0 = (uint32_t)(warp_m * 32 + laneRow) * 256;          // mi=0
    uint32_t bOff0 = (uint32_t)(warp_n * 32 + laneRow) * 256;          // n2=0
    uint32_t uo[8];
    #pragma unroll
    for (int kk = 0; kk < 8; kk++)
        uo[kk] = ((uint32_t)((2 * kk + colSel) * 16)) ^ mask;

    float scp[2][2];
    scp[0][0] = scp[0][1] = scp[1][0] = scp[1][1] = 0.f;

    int pc = 0;
    for (int och = 0; och < NOCH; och++) {
        float acc[2][4][4];
        #pragma unroll
        for (int mi = 0; mi < 2; mi++)
            #pragma unroll
            for (int ni = 0; ni < 4; ni++)
                #pragma unroll
                for (int q = 0; q < 4; q++) acc[mi][ni][q] = 0.f;

        for (int kc = 0; kc < 8; kc++, pc++) {
            CP_WAIT0();
            __syncthreads();
            if (pc + 1 < NC) { issue_chunk(pc + 1); CP_COMMIT(); }

            uint32_t tb = sb + (uint32_t)(pc & 1) * BUF_SZ;
            uint32_t aB0 = tb + OFF_A + aOff0;          // mi=0 rows
            uint32_t aB1 = aB0 + 4096;                  // mi=1 (+16 rows)
            uint32_t bB0 = tb + OFF_B + bOff0;          // n2=0 rows
            uint32_t bB1 = bB0 + 4096;                  // n2=1 (+16 rows)

            #pragma unroll
            for (int kk = 0; kk < 8; kk++) {
                uint32_t ar[2][4], br0[4], br1[4];
                ldsm4(ar[0], aB0 + uo[kk]);
                ldsm4(ar[1], aB1 + uo[kk]);
                ldsm4(br0, bB0 + uo[kk]);
                ldsm4(br1, bB1 + uo[kk]);
                // register tf32 conversion (rna)
                #pragma unroll
                for (int q = 0; q < 4; q++) {
                    ar[0][q] = tf32r(ar[0][q]);
                    ar[1][q] = tf32r(ar[1][q]);
                    br0[q]   = tf32r(br0[q]);
                    br1[q]   = tf32r(br1[q]);
                }
                #pragma unroll
                for (int mi = 0; mi < 2; mi++) {
                    mma_tf32(acc[mi][0], ar[mi], br0[0], br0[2]);
                    mma_tf32(acc[mi][1], ar[mi], br0[1], br0[3]);
                    mma_tf32(acc[mi][2], ar[mi], br1[0], br1[2]);
                    mma_tf32(acc[mi][3], ar[mi], br1[1], br1[3]);
                }
            }
        }

        int o0 = (ochb + och) * 128;
        #pragma unroll
        for (int mi = 0; mi < 2; mi++) {
            int r0 = warp_m * 32 + mi * 16 + (L >> 2);
            float la0 = laF[r0],     la1 = laF[r0 + 1], la2 = laF[r0 + 2];
            float lb0 = laF[r0 + 8], lb1 = laF[r0 + 9], lb2 = laF[r0 + 10];
            #pragma unroll
            for (int ni = 0; ni < 4; ni++) {
                int c0 = o0 + warp_n * 32 + ni * 8 + (L & 3) * 2;
                float2 qb = *(const float2*)(qbF + c0);
                float2 w0 = *(const float2*)(w0F + c0);
                float2 w1 = *(const float2*)(w1F + c0);
                float2 w2 = *(const float2*)(w2F + c0);
                float2 sw = *(const float2*)(swF + c0);
                float cva0 = w0.x * la0 + w1.x * la1 + w2.x * la2 + qb.x;
                float cva1 = w0.y * la0 + w1.y * la1 + w2.y * la2 + qb.y;
                float cvb0 = w0.x * lb0 + w1.x * lb1 + w2.x * lb2 + qb.x;
                float cvb1 = w0.y * lb0 + w1.y * lb1 + w2.y * lb2 + qb.y;
                scp[mi][0] += sw.x * ftanh(acc[mi][ni][0] + cva0)
                            + sw.y * ftanh(acc[mi][ni][1] + cva1);
                scp[mi][1] += sw.x * ftanh(acc[mi][ni][2] + cvb0)
                            + sw.y * ftanh(acc[mi][ni][3] + cvb1);
            }
        }
    }

    // partial score for 256 columns -> global accumulator
    #pragma unroll
    for (int mi = 0; mi < 2; mi++)
        #pragma unroll
        for (int h = 0; h < 2; h++) {
            float v = scp[mi][h];
            v += __shfl_xor_sync(0xffffffffu, v, 1);
            v += __shfl_xor_sync(0xffffffffu, v, 2);
            if ((L & 3) == 0) {
                int r = warp_m * 32 + mi * 16 + (L >> 2) + h * 8;
                atomicAdd(&g_scr[b * TT + t0 + r], v);
            }
        }
}

// ---------------- sigmoid + per-batch sum -----------------------------------
__global__ void __launch_bounds__(256)
k_sig(const float* __restrict__ s_b) {
    int i = blockIdx.x * 256 + threadIdx.x;        // 65536 elems
    float p = __fdividef(1.f, 1.f + __expf(-(g_scr[i] + s_b[0])));
    g_p[i] = p;
    #pragma unroll
    for (int off = 16; off; off >>= 1)
        p += __shfl_xor_sync(0xffffffffu, p, off);
    if ((threadIdx.x & 31) == 0) atomicAdd(&g_sum[i >> 11], p);
}

// ---------------- context: g_ctx[b,h] += sum_t p[b,t]*value[b,t,h] ----------
__global__ void __launch_bounds__(256)
k_ctx(const float* __restrict__ value) {
    int b = blockIdx.x, ts = blockIdx.y;
    int h2 = threadIdx.x;                       // float2 column index (0..255)
    const float2* vb = (const float2*)value + ((long)b * TT + ts * 256) * 256 + h2;
    const float* pb  = g_p + b * TT + ts * 256;
    float2 a0 = {0.f, 0.f}, a1 = {0.f, 0.f}, a2 = {0.f, 0.f}, a3 = {0.f, 0.f};
    #pragma unroll 4
    for (int t = 0; t < 256; t += 4) {
        float p0 = pb[t], p1 = pb[t + 1], p2 = pb[t + 2], p3 = pb[t + 3];
        float2 v0 = vb[(long)(t + 0) * 256];
        float2 v1 = vb[(long)(t + 1) * 256];
        float2 v2 = vb[(long)(t + 2) * 256];
        float2 v3 = vb[(long)(t + 3) * 256];
        a0.x += p0 * v0.x; a0.y += p0 * v0.y;
        a1.x += p1 * v1.x; a1.y += p1 * v1.y;
        a2.x += p2 * v2.x; a2.y += p2 * v2.y;
        a3.x += p3 * v3.x; a3.y += p3 * v3.y;
    }
    float rx = (a0.x + a1.x) + (a2.x + a3.x);
    float ry = (a0.y + a1.y) + (a2.y + a3.y);
    atomicAdd(&g_ctx[b * HH + 2 * h2 + 0], rx);
    atomicAdd(&g_ctx[b * HH + 2 * h2 + 1], ry);
}

__global__ void k_fin(float* __restrict__ out) {
    int i = blockIdx.x * 256 + threadIdx.x;
    if (i < BB * HH) out[i] = g_ctx[i] / g_sum[i / HH];
    if (i < BB * TT) out[BB * HH + i] = g_p[i] / g_sum[i / TT];
}

// ---------------------------------------------------------------------------
extern "C" void kernel_launch(void* const* d_in, const int* in_sizes, int n_in,
                              void* d_out, int out_size) {
    const float* query  = (const float*)d_in[0];
    const float* value  = (const float*)d_in[1];
    const float* la     = (const float*)d_in[2];
    const float* conv_w = (const float*)d_in[3];
    const float* conv_b = (const float*)d_in[4];
    const float* q_w    = (const float*)d_in[5];
    const float* v_w    = (const float*)d_in[6];
    const float* s_w    = (const float*)d_in[7];
    const float* s_b    = (const float*)d_in[8];
    const float* bias   = (const float*)d_in[9];
    float* out = (float*)d_out;

    cudaFuncSetAttribute(k_main, cudaFuncAttributeMaxDynamicSharedMemorySize,
                         SMEM_REQ);

    k_init<<<(BB * TT + 255) / 256, 256>>>();
    k_qproj<<<HH, 256>>>(query, q_w);
    k_main<<<dim3((TT / MT) * 2, BB), 256, SMEM_REQ>>>(value, v_w, la, conv_w,
                                                       conv_b, s_w, bias);
    k_sig<<<BB * TT / 256, 256>>>(s_b);
    k_ctx<<<dim3(BB, 8), 256>>>(value);
    k_fin<<<(BB * TT + 255) / 256, 256>>>(out);
}

// round 14
// speedup vs baseline: 1.2880x; 1.1281x over previous
#include <cuda_runtime.h>
#include <cuda_bf16.h>
#include <math.h>
#include <stdint.h>

#define BB 32
#define TT 2048
#define HH 512

#define MT  64                  // t-rows per CTA
#define KC  64                  // K-chunk (fp32 elements)
#define NOCH 2                  // N chunks of 128 per CTA (half of total)
#define NC  (NOCH * (HH / KC))  // 16 chunks per CTA

// ---------------- scratch (device globals; no allocation allowed) ----------
__device__ float g_q[BB * HH];
__device__ float g_p[BB * TT];
__device__ float g_scr[BB * TT];    // raw score accumulator (pre-sigmoid)
__device__ float g_ctx[BB * HH];
__device__ float g_sum[BB];
__device__ float g_vwt[HH * HH];    // v_w pre-rounded to tf32 (rna)

// ---------------- SMEM layout (byte offsets from 1024-aligned base) --------
// buffer: [A 16K fp32 64x64][B 32K fp32 128x64] ; rows 256B pitch, swizzled
#define OFF_A    0
#define OFF_B    16384
#define BUF_SZ   49152
#define OFF_QB   98304
#define OFF_W0   100352
#define OFF_W1   102400
#define OFF_W2   104448
#define OFF_SW   106496
#define OFF_LA   108544    // 66 floats
#define SMEM_END 109056
#define SMEM_REQ (SMEM_END + 1024)   // x2 CTAs <= 227KB

// ---------------- helpers ---------------------------------------------------
__device__ __forceinline__ uint32_t smem_u32(const void* p) {
    uint32_t a;
    asm("{ .reg .u64 t; cvta.to.shared.u64 t, %1; cvt.u32.u64 %0, t; }"
        : "=r"(a) : "l"(p));
    return a;
}
__device__ __forceinline__ uint64_t gaddr(const void* p) {
    uint64_t a;
    asm("cvta.to.global.u64 %0, %1;" : "=l"(a) : "l"(p));
    return a;
}
__device__ __forceinline__ void cpa16(uint32_t d, uint64_t s) {
    asm volatile("cp.async.cg.shared.global [%0], [%1], 16;"
                 :: "r"(d), "l"(s) : "memory");
}
#define CP_COMMIT() asm volatile("cp.async.commit_group;" ::: "memory")
#define CP_WAIT0()  asm volatile("cp.async.wait_group 0;" ::: "memory")

__device__ __forceinline__ void ldsm4(uint32_t* r, uint32_t a) {
    asm volatile("ldmatrix.sync.aligned.m8n8.x4.shared.b16 {%0,%1,%2,%3}, [%4];"
                 : "=r"(r[0]), "=r"(r[1]), "=r"(r[2]), "=r"(r[3]) : "r"(a));
}
__device__ __forceinline__ void mma_tf32(float* d, const uint32_t* a,
                                         uint32_t b0, uint32_t b1) {
    asm volatile(
        "mma.sync.aligned.m16n8k8.row.col.f32.tf32.tf32.f32 "
        "{%0,%1,%2,%3},{%4,%5,%6,%7},{%8,%9},{%0,%1,%2,%3};"
        : "+f"(d[0]), "+f"(d[1]), "+f"(d[2]), "+f"(d[3])
        : "r"(a[0]), "r"(a[1]), "r"(a[2]), "r"(a[3]), "r"(b0), "r"(b1));
}
__device__ __forceinline__ uint32_t tf32r(uint32_t x) {
    uint32_t y;
    asm("cvt.rna.tf32.f32 %0, %1;" : "=r"(y) : "f"(__uint_as_float(x)));
    return y;
}
__device__ __forceinline__ float ftanh(float x) {
    float y;
    asm("tanh.approx.f32 %0, %1;" : "=f"(y) : "f"(x));
    return y;
}

// ---------------- init: zero accumulators + pre-round v_w to tf32 ----------
__global__ void __launch_bounds__(256)
k_init(const float* __restrict__ v_w) {
    int i = blockIdx.x * 256 + threadIdx.x;        // 65536 threads
    if (i < BB * HH) g_ctx[i] = 0.f;
    if (i < BB)      g_sum[i] = 0.f;
    g_scr[i] = 0.f;                                // BB*TT == 65536
    float4 v = ((const float4*)v_w)[i];            // HH*HH/4 == 65536
    uint4 r;
    r.x = tf32r(__float_as_uint(v.x));
    r.y = tf32r(__float_as_uint(v.y));
    r.z = tf32r(__float_as_uint(v.z));
    r.w = tf32r(__float_as_uint(v.w));
    ((uint4*)g_vwt)[i] = r;
}

// q[b,o]: one block per o; warp w covers b in [4w, 4w+4)
__global__ void __launch_bounds__(256)
k_qproj(const float* __restrict__ query, const float* __restrict__ q_w) {
    int o = blockIdx.x, lane = threadIdx.x & 31, warp = threadIdx.x >> 5;
    const float* wrow = q_w + o * HH;
    float acc0 = 0.f, acc1 = 0.f, acc2 = 0.f, acc3 = 0.f;
    int b0 = warp * 4;
    for (int k = lane; k < HH; k += 32) {
        float w = __ldg(wrow + k);
        acc0 += w * __ldg(query + (b0 + 0) * HH + k);
        acc1 += w * __ldg(query + (b0 + 1) * HH + k);
        acc2 += w * __ldg(query + (b0 + 2) * HH + k);
        acc3 += w * __ldg(query + (b0 + 3) * HH + k);
    }
    #pragma unroll
    for (int off = 16; off; off >>= 1) {
        acc0 += __shfl_xor_sync(0xffffffffu, acc0, off);
        acc1 += __shfl_xor_sync(0xffffffffu, acc1, off);
        acc2 += __shfl_xor_sync(0xffffffffu, acc2, off);
        acc3 += __shfl_xor_sync(0xffffffffu, acc3, off);
    }
    if (lane == 0) {
        g_q[(b0 + 0) * HH + o] = acc0;
        g_q[(b0 + 1) * HH + o] = acc1;
        g_q[(b0 + 2) * HH + o] = acc2;
        g_q[(b0 + 3) * HH + o] = acc3;
    }
}

// ---------------- main TF32 MMA kernel --------------------------------------
// CTA = (b, t-tile of 64, N-half of 256). grid (64, 32): x = t-tile*2 + nh.
// A = raw value fp32 (cvt.rna in regs); B = pre-rounded tf32 (no in-loop cvt).
__global__ void __launch_bounds__(256, 2)
k_main(const float* __restrict__ value, const float* __restrict__ la,
       const float* __restrict__ conv_w, const float* __restrict__ conv_b,
       const float* __restrict__ s_w,    const float* __restrict__ bias)
{
    extern __shared__ char smraw[];
    uint32_t raw = smem_u32(smraw);
    uint32_t sb  = (raw + 1023) & ~1023u;
    char* base   = smraw + (sb - raw);

    int tid = threadIdx.x, L = tid & 31, wid = tid >> 5;
    int warp_m = wid >> 2, warp_n = wid & 3;      // 2 x 4
    int b  = blockIdx.y;
    int t0 = (blockIdx.x >> 1) * MT;
    int ochb = (blockIdx.x & 1) * NOCH;           // global o-chunk base (0 or 2)

    uint64_t valG = gaddr(value) + (uint64_t)(((long)b * TT + t0) * HH) * 4;
    uint64_t vwG  = gaddr(g_vwt);

    // per chunk: A 64x16 units (1024) + B 128x16 units (2048) = 3072; 12/thread
    auto issue_chunk = [&](int pc) {
        int och = ochb + (pc >> 3), kc = pc & 7;
        int kt = kc * KC, o0 = och * 128;
        uint32_t tb = sb + (uint32_t)(pc & 1) * BUF_SZ;
        #pragma unroll
        for (int i = 0; i < 12; i++) {
            int id = tid + i * 256;
            if (id < 1024) {               // A fp32: row pitch 256B
                int r = id >> 4, u = id & 15;
                uint32_t so = (uint32_t)(r * 256 + ((u * 16) ^ ((r & 7) << 4)));
                uint64_t ga = (uint64_t)((long)r * HH + kt + u * 4) * 4;
                cpa16(tb + OFF_A + so, valG + ga);
            } else {                       // B tf32: row pitch 256B
                int id2 = id - 1024;
                int r = id2 >> 4, u = id2 & 15;
                uint32_t so = (uint32_t)(r * 256 + ((u * 16) ^ ((r & 7) << 4)));
                uint64_t gb = (uint64_t)((long)(o0 + r) * HH + kt + u * 4) * 4;
                cpa16(tb + OFF_B + so, vwG + gb);
            }
        }
    };

    issue_chunk(0);
    CP_COMMIT();

    float* qbF = (float*)(base + OFF_QB);
    float* w0F = (float*)(base + OFF_W0);
    float* w1F = (float*)(base + OFF_W1);
    float* w2F = (float*)(base + OFF_W2);
    float* swF = (float*)(base + OFF_SW);
    float* laF = (float*)(base + OFF_LA);
    for (int i = tid; i < HH; i += 256) {
        qbF[i] = g_q[b * HH + i] + bias[i] + conv_b[i];
        w0F[i] = conv_w[i * 3 + 0];
        w1F[i] = conv_w[i * 3 + 1];
        w2F[i] = conv_w[i * 3 + 2];
        swF[i] = s_w[i];
    }
    if (tid < MT + 2) {
        int gt = t0 - 1 + tid;
        laF[tid] = (gt >= 0 && gt < TT) ? la[b * TT + gt] : 0.f;
    }

    // ldmatrix lane constants (shared form for A and B):
    uint32_t laneRow = (uint32_t)((L & 7) + ((L >> 3) & 1) * 8);
    uint32_t colSel  = (uint32_t)(L >> 4);
    uint32_t mask    = (uint32_t)(L & 7) << 4;
    uint32_t aOff0 = (uint32_t)(warp_m * 32 + laneRow) * 256;          // mi=0
    uint32_t bOff0 = (uint32_t)(warp_n * 32 + laneRow) * 256;          // n2=0
    uint32_t uo[8];
    #pragma unroll
    for (int kk = 0; kk < 8; kk++)
        uo[kk] = ((uint32_t)((2 * kk + colSel) * 16)) ^ mask;

    float scp[2][2];
    scp[0][0] = scp[0][1] = scp[1][0] = scp[1][1] = 0.f;

    int pc = 0;
    for (int och = 0; och < NOCH; och++) {
        float acc[2][4][4];
        #pragma unroll
        for (int mi = 0; mi < 2; mi++)
            #pragma unroll
            for (int ni = 0; ni < 4; ni++)
                #pragma unroll
                for (int q = 0; q < 4; q++) acc[mi][ni][q] = 0.f;

        for (int kc = 0; kc < 8; kc++, pc++) {
            CP_WAIT0();
            __syncthreads();
            if (pc + 1 < NC) { issue_chunk(pc + 1); CP_COMMIT(); }

            uint32_t tb = sb + (uint32_t)(pc & 1) * BUF_SZ;
            uint32_t aB0 = tb + OFF_A + aOff0;          // mi=0 rows
            uint32_t aB1 = aB0 + 4096;                  // mi=1 (+16 rows)
            uint32_t bB0 = tb + OFF_B + bOff0;          // n2=0 rows
            uint32_t bB1 = bB0 + 4096;                  // n2=1 (+16 rows)

            #pragma unroll
            for (int kk = 0; kk < 8; kk++) {
                uint32_t ar[2][4], br0[4], br1[4];
                ldsm4(ar[0], aB0 + uo[kk]);
                ldsm4(ar[1], aB1 + uo[kk]);
                ldsm4(br0, bB0 + uo[kk]);
                ldsm4(br1, bB1 + uo[kk]);
                // A only: register tf32 conversion (rna); B pre-rounded
                #pragma unroll
                for (int q = 0; q < 4; q++) {
                    ar[0][q] = tf32r(ar[0][q]);
                    ar[1][q] = tf32r(ar[1][q]);
                }
                #pragma unroll
                for (int mi = 0; mi < 2; mi++) {
                    mma_tf32(acc[mi][0], ar[mi], br0[0], br0[2]);
                    mma_tf32(acc[mi][1], ar[mi], br0[1], br0[3]);
                    mma_tf32(acc[mi][2], ar[mi], br1[0], br1[2]);
                    mma_tf32(acc[mi][3], ar[mi], br1[1], br1[3]);
                }
            }
        }

        int o0 = (ochb + och) * 128;
        #pragma unroll
        for (int mi = 0; mi < 2; mi++) {
            int r0 = warp_m * 32 + mi * 16 + (L >> 2);
            float la0 = laF[r0],     la1 = laF[r0 + 1], la2 = laF[r0 + 2];
            float lb0 = laF[r0 + 8], lb1 = laF[r0 + 9], lb2 = laF[r0 + 10];
            #pragma unroll
            for (int ni = 0; ni < 4; ni++) {
                int c0 = o0 + warp_n * 32 + ni * 8 + (L & 3) * 2;
                float2 qb = *(const float2*)(qbF + c0);
                float2 w0 = *(const float2*)(w0F + c0);
                float2 w1 = *(const float2*)(w1F + c0);
                float2 w2 = *(const float2*)(w2F + c0);
                float2 sw = *(const float2*)(swF + c0);
                float cva0 = w0.x * la0 + w1.x * la1 + w2.x * la2 + qb.x;
                float cva1 = w0.y * la0 + w1.y * la1 + w2.y * la2 + qb.y;
                float cvb0 = w0.x * lb0 + w1.x * lb1 + w2.x * lb2 + qb.x;
                float cvb1 = w0.y * lb0 + w1.y * lb1 + w2.y * lb2 + qb.y;
                scp[mi][0] += sw.x * ftanh(acc[mi][ni][0] + cva0)
                            + sw.y * ftanh(acc[mi][ni][1] + cva1);
                scp[mi][1] += sw.x * ftanh(acc[mi][ni][2] + cvb0)
                            + sw.y * ftanh(acc[mi][ni][3] + cvb1);
            }
        }
    }

    // partial score for 256 columns -> global accumulator
    #pragma unroll
    for (int mi = 0; mi < 2; mi++)
        #pragma unroll
        for (int h = 0; h < 2; h++) {
            float v = scp[mi][h];
            v += __shfl_xor_sync(0xffffffffu, v, 1);
            v += __shfl_xor_sync(0xffffffffu, v, 2);
            if ((L & 3) == 0) {
                int r = warp_m * 32 + mi * 16 + (L >> 2) + h * 8;
                atomicAdd(&g_scr[b * TT + t0 + r], v);
            }
        }
}

// ---------------- fused sigmoid + context -----------------------------------
// block (b, ts): compute p for its 256 t-values, then accumulate context.
__global__ void __launch_bounds__(256)
k_ctx(const float* __restrict__ value, const float* __restrict__ s_b) {
    __shared__ float ps[256];
    int b = blockIdx.x, ts = blockIdx.y;
    int tix = threadIdx.x;

    // sigmoid + write g_p + per-batch sum
    {
        int t = ts * 256 + tix;
        float p = __fdividef(1.f, 1.f + __expf(-(g_scr[b * TT + t] + s_b[0])));
        g_p[b * TT + t] = p;
        ps[tix] = p;
        float ws = p;
        #pragma unroll
        for (int off = 16; off; off >>= 1)
            ws += __shfl_xor_sync(0xffffffffu, ws, off);
        if ((tix & 31) == 0) atomicAdd(&g_sum[b], ws);
    }
    __syncthreads();

    int h2 = tix;                               // float2 column index (0..255)
    const float2* vb = (const float2*)value + ((long)b * TT + ts * 256) * 256 + h2;
    float2 a0 = {0.f, 0.f}, a1 = {0.f, 0.f}, a2 = {0.f, 0.f}, a3 = {0.f, 0.f};
    #pragma unroll 4
    for (int t = 0; t < 256; t += 4) {
        float p0 = ps[t], p1 = ps[t + 1], p2 = ps[t + 2], p3 = ps[t + 3];
        float2 v0 = vb[(long)(t + 0) * 256];
        float2 v1 = vb[(long)(t + 1) * 256];
        float2 v2 = vb[(long)(t + 2) * 256];
        float2 v3 = vb[(long)(t + 3) * 256];
        a0.x += p0 * v0.x; a0.y += p0 * v0.y;
        a1.x += p1 * v1.x; a1.y += p1 * v1.y;
        a2.x += p2 * v2.x; a2.y += p2 * v2.y;
        a3.x += p3 * v3.x; a3.y += p3 * v3.y;
    }
    float rx = (a0.x + a1.x) + (a2.x + a3.x);
    float ry = (a0.y + a1.y) + (a2.y + a3.y);
    atomicAdd(&g_ctx[b * HH + 2 * h2 + 0], rx);
    atomicAdd(&g_ctx[b * HH + 2 * h2 + 1], ry);
}

__global__ void k_fin(float* __restrict__ out) {
    int i = blockIdx.x * 256 + threadIdx.x;
    if (i < BB * HH) out[i] = g_ctx[i] / g_sum[i / HH];
    if (i < BB * TT) out[BB * HH + i] = g_p[i] / g_sum[i / TT];
}

// ---------------------------------------------------------------------------
extern "C" void kernel_launch(void* const* d_in, const int* in_sizes, int n_in,
                              void* d_out, int out_size) {
    const float* query  = (const float*)d_in[0];
    const float* value  = (const float*)d_in[1];
    const float* la     = (const float*)d_in[2];
    const float* conv_w = (const float*)d_in[3];
    const float* conv_b = (const float*)d_in[4];
    const float* q_w    = (const float*)d_in[5];
    const float* v_w    = (const float*)d_in[6];
    const float* s_w    = (const float*)d_in[7];
    const float* s_b    = (const float*)d_in[8];
    const float* bias   = (const float*)d_in[9];
    float* out = (float*)d_out;

    cudaFuncSetAttribute(k_main, cudaFuncAttributeMaxDynamicSharedMemorySize,
                         SMEM_REQ);

    k_init<<<256, 256>>>(v_w);
    k_qproj<<<HH, 256>>>(query, q_w);
    k_main<<<dim3((TT / MT) * 2, BB), 256, SMEM_REQ>>>(value, la, conv_w,
                                                       conv_b, s_w, bias);
    k_ctx<<<dim3(BB, 8), 256>>>(value, s_b);
    k_fin<<<(BB * TT + 255) / 256, 256>>>(out);
}

// round 15
// speedup vs baseline: 1.3794x; 1.0709x over previous
#include <cuda_runtime.h>
#include <cuda_bf16.h>
#include <math.h>
#include <stdint.h>

#define BB 32
#define TT 2048
#define HH 512

#define MT  64                  // t-rows per CTA
#define KC  64                  // K-chunk (fp32 elements)
#define NOCH 2                  // N chunks of 128 per CTA (half of total)
#define NC  (NOCH * (HH / KC))  // 16 chunks per CTA

// ---------------- scratch (device globals; no allocation allowed) ----------
__device__ float g_q[BB * HH];
__device__ float g_p[BB * TT];
__device__ float g_scr[BB * TT];    // raw score accumulator (pre-sigmoid)
__device__ float g_ctx[BB * HH];
__device__ float g_sum[BB];
__device__ float g_vwt[HH * HH];    // v_w pre-rounded to tf32 (rna)

// ---------------- SMEM layout (byte offsets from 1024-aligned base) --------
// buffer: [A 16K fp32 64x64][B 32K tf32 128x64] ; rows 256B pitch, swizzled
#define OFF_A    0
#define OFF_B    16384
#define BUF_SZ   49152
#define OFF_QB   98304
#define OFF_W0   100352
#define OFF_W1   102400
#define OFF_W2   104448
#define OFF_SW   106496
#define OFF_LA   108544    // 66 floats
#define SMEM_END 109056
#define SMEM_REQ (SMEM_END + 1024)   // x2 CTAs <= 227KB

// ---------------- helpers ---------------------------------------------------
__device__ __forceinline__ uint32_t smem_u32(const void* p) {
    uint32_t a;
    asm("{ .reg .u64 t; cvta.to.shared.u64 t, %1; cvt.u32.u64 %0, t; }"
        : "=r"(a) : "l"(p));
    return a;
}
__device__ __forceinline__ uint64_t gaddr(const void* p) {
    uint64_t a;
    asm("cvta.to.global.u64 %0, %1;" : "=l"(a) : "l"(p));
    return a;
}
__device__ __forceinline__ void cpa16(uint32_t d, uint64_t s) {
    asm volatile("cp.async.cg.shared.global [%0], [%1], 16;"
                 :: "r"(d), "l"(s) : "memory");
}
#define CP_COMMIT() asm volatile("cp.async.commit_group;" ::: "memory")
#define CP_WAIT0()  asm volatile("cp.async.wait_group 0;" ::: "memory")

__device__ __forceinline__ void ldsm4(uint32_t* r, uint32_t a) {
    asm volatile("ldmatrix.sync.aligned.m8n8.x4.shared.b16 {%0,%1,%2,%3}, [%4];"
                 : "=r"(r[0]), "=r"(r[1]), "=r"(r[2]), "=r"(r[3]) : "r"(a));
}
__device__ __forceinline__ void mma_tf32(float* d, const uint32_t* a,
                                         uint32_t b0, uint32_t b1) {
    asm volatile(
        "mma.sync.aligned.m16n8k8.row.col.f32.tf32.tf32.f32 "
        "{%0,%1,%2,%3},{%4,%5,%6,%7},{%8,%9},{%0,%1,%2,%3};"
        : "+f"(d[0]), "+f"(d[1]), "+f"(d[2]), "+f"(d[3])
        : "r"(a[0]), "r"(a[1]), "r"(a[2]), "r"(a[3]), "r"(b0), "r"(b1));
}
__device__ __forceinline__ uint32_t tf32r(uint32_t x) {
    uint32_t y;
    asm("cvt.rna.tf32.f32 %0, %1;" : "=r"(y) : "f"(__uint_as_float(x)));
    return y;
}
__device__ __forceinline__ float ftanh(float x) {
    float y;
    asm("tanh.approx.f32 %0, %1;" : "=f"(y) : "f"(x));
    return y;
}

// ---------------- init: zero accumulators + pre-round v_w to tf32 ----------
__global__ void __launch_bounds__(256)
k_init(const float* __restrict__ v_w) {
    int i = blockIdx.x * 256 + threadIdx.x;        // 65536 threads
    if (i < BB * HH) g_ctx[i] = 0.f;
    if (i < BB)      g_sum[i] = 0.f;
    g_scr[i] = 0.f;                                // BB*TT == 65536
    float4 v = ((const float4*)v_w)[i];            // HH*HH/4 == 65536
    uint4 r;
    r.x = tf32r(__float_as_uint(v.x));
    r.y = tf32r(__float_as_uint(v.y));
    r.z = tf32r(__float_as_uint(v.z));
    r.w = tf32r(__float_as_uint(v.w));
    ((uint4*)g_vwt)[i] = r;
}

// q[b,o]: one block per o; warp w covers b in [4w, 4w+4)
__global__ void __launch_bounds__(256)
k_qproj(const float* __restrict__ query, const float* __restrict__ q_w) {
    int o = blockIdx.x, lane = threadIdx.x & 31, warp = threadIdx.x >> 5;
    const float* wrow = q_w + o * HH;
    float acc0 = 0.f, acc1 = 0.f, acc2 = 0.f, acc3 = 0.f;
    int b0 = warp * 4;
    for (int k = lane; k < HH; k += 32) {
        float w = __ldg(wrow + k);
        acc0 += w * __ldg(query + (b0 + 0) * HH + k);
        acc1 += w * __ldg(query + (b0 + 1) * HH + k);
        acc2 += w * __ldg(query + (b0 + 2) * HH + k);
        acc3 += w * __ldg(query + (b0 + 3) * HH + k);
    }
    #pragma unroll
    for (int off = 16; off; off >>= 1) {
        acc0 += __shfl_xor_sync(0xffffffffu, acc0, off);
        acc1 += __shfl_xor_sync(0xffffffffu, acc1, off);
        acc2 += __shfl_xor_sync(0xffffffffu, acc2, off);
        acc3 += __shfl_xor_sync(0xffffffffu, acc3, off);
    }
    if (lane == 0) {
        g_q[(b0 + 0) * HH + o] = acc0;
        g_q[(b0 + 1) * HH + o] = acc1;
        g_q[(b0 + 2) * HH + o] = acc2;
        g_q[(b0 + 3) * HH + o] = acc3;
    }
}

// ---------------- main TF32 MMA kernel --------------------------------------
// CTA = (b, t-tile of 64, N-half of 256). grid (64, 32): x = t-tile*2 + nh.
// A = raw value fp32 fed directly to tf32 MMA (HW truncates mantissa);
// B = pre-rounded tf32 (rna). No in-loop cvt at all.
__global__ void __launch_bounds__(256, 2)
k_main(const float* __restrict__ value, const float* __restrict__ la,
       const float* __restrict__ conv_w, const float* __restrict__ conv_b,
       const float* __restrict__ s_w,    const float* __restrict__ bias)
{
    extern __shared__ char smraw[];
    uint32_t raw = smem_u32(smraw);
    uint32_t sb  = (raw + 1023) & ~1023u;
    char* base   = smraw + (sb - raw);

    int tid = threadIdx.x, L = tid & 31, wid = tid >> 5;
    int warp_m = wid >> 2, warp_n = wid & 3;      // 2 x 4
    int b  = blockIdx.y;
    int t0 = (blockIdx.x >> 1) * MT;
    int ochb = (blockIdx.x & 1) * NOCH;           // global o-chunk base (0 or 2)

    uint64_t valG = gaddr(value) + (uint64_t)(((long)b * TT + t0) * HH) * 4;
    uint64_t vwG  = gaddr(g_vwt);

    // per chunk: A 64x16 units (1024) + B 128x16 units (2048) = 3072; 12/thread
    auto issue_chunk = [&](int pc) {
        int och = ochb + (pc >> 3), kc = pc & 7;
        int kt = kc * KC, o0 = och * 128;
        uint32_t tb = sb + (uint32_t)(pc & 1) * BUF_SZ;
        #pragma unroll
        for (int i = 0; i < 12; i++) {
            int id = tid + i * 256;
            if (id < 1024) {               // A fp32: row pitch 256B
                int r = id >> 4, u = id & 15;
                uint32_t so = (uint32_t)(r * 256 + ((u * 16) ^ ((r & 7) << 4)));
                uint64_t ga = (uint64_t)((long)r * HH + kt + u * 4) * 4;
                cpa16(tb + OFF_A + so, valG + ga);
            } else {                       // B tf32: row pitch 256B
                int id2 = id - 1024;
                int r = id2 >> 4, u = id2 & 15;
                uint32_t so = (uint32_t)(r * 256 + ((u * 16) ^ ((r & 7) << 4)));
                uint64_t gb = (uint64_t)((long)(o0 + r) * HH + kt + u * 4) * 4;
                cpa16(tb + OFF_B + so, vwG + gb);
            }
        }
    };

    issue_chunk(0);
    CP_COMMIT();

    float* qbF = (float*)(base + OFF_QB);
    float* w0F = (float*)(base + OFF_W0);
    float* w1F = (float*)(base + OFF_W1);
    float* w2F = (float*)(base + OFF_W2);
    float* swF = (float*)(base + OFF_SW);
    float* laF = (float*)(base + OFF_LA);
    for (int i = tid; i < HH; i += 256) {
        qbF[i] = g_q[b * HH + i] + bias[i] + conv_b[i];
        w0F[i] = conv_w[i * 3 + 0];
        w1F[i] = conv_w[i * 3 + 1];
        w2F[i] = conv_w[i * 3 + 2];
        swF[i] = s_w[i];
    }
    if (tid < MT + 2) {
        int gt = t0 - 1 + tid;
        laF[tid] = (gt >= 0 && gt < TT) ? la[b * TT + gt] : 0.f;
    }

    // ldmatrix lane constants (shared form for A and B):
    uint32_t laneRow = (uint32_t)((L & 7) + ((L >> 3) & 1) * 8);
    uint32_t colSel  = (uint32_t)(L >> 4);
    uint32_t mask    = (uint32_t)(L & 7) << 4;
    uint32_t aOff0 = (uint32_t)(warp_m * 32 + laneRow) * 256;          // mi=0
    uint32_t bOff0 = (uint32_t)(warp_n * 32 + laneRow) * 256;          // n2=0
    uint32_t uo[8];
    #pragma unroll
    for (int kk = 0; kk < 8; kk++)
        uo[kk] = ((uint32_t)((2 * kk + colSel) * 16)) ^ mask;

    float scp[2][2];
    scp[0][0] = scp[0][1] = scp[1][0] = scp[1][1] = 0.f;

    int pc = 0;
    for (int och = 0; och < NOCH; och++) {
        float acc[2][4][4];
        #pragma unroll
        for (int mi = 0; mi < 2; mi++)
            #pragma unroll
            for (int ni = 0; ni < 4; ni++)
                #pragma unroll
                for (int q = 0; q < 4; q++) acc[mi][ni][q] = 0.f;

        for (int kc = 0; kc < 8; kc++, pc++) {
            CP_WAIT0();
            __syncthreads();
            if (pc + 1 < NC) { issue_chunk(pc + 1); CP_COMMIT(); }

            uint32_t tb = sb + (uint32_t)(pc & 1) * BUF_SZ;
            uint32_t aB0 = tb + OFF_A + aOff0;          // mi=0 rows
            uint32_t aB1 = aB0 + 4096;                  // mi=1 (+16 rows)
            uint32_t bB0 = tb + OFF_B + bOff0;          // n2=0 rows
            uint32_t bB1 = bB0 + 4096;                  // n2=1 (+16 rows)

            #pragma unroll
            for (int kk = 0; kk < 8; kk++) {
                uint32_t ar[2][4], br0[4], br1[4];
                ldsm4(ar[0], aB0 + uo[kk]);
                ldsm4(ar[1], aB1 + uo[kk]);
                ldsm4(br0, bB0 + uo[kk]);
                ldsm4(br1, bB1 + uo[kk]);
                // no cvt: A raw fp32 bits (HW truncation), B pre-rounded tf32
                #pragma unroll
                for (int mi = 0; mi < 2; mi++) {
                    mma_tf32(acc[mi][0], ar[mi], br0[0], br0[2]);
                    mma_tf32(acc[mi][1], ar[mi], br0[1], br0[3]);
                    mma_tf32(acc[mi][2], ar[mi], br1[0], br1[2]);
                    mma_tf32(acc[mi][3], ar[mi], br1[1], br1[3]);
                }
            }
        }

        int o0 = (ochb + och) * 128;
        #pragma unroll
        for (int mi = 0; mi < 2; mi++) {
            int r0 = warp_m * 32 + mi * 16 + (L >> 2);
            float la0 = laF[r0],     la1 = laF[r0 + 1], la2 = laF[r0 + 2];
            float lb0 = laF[r0 + 8], lb1 = laF[r0 + 9], lb2 = laF[r0 + 10];
            #pragma unroll
            for (int ni = 0; ni < 4; ni++) {
                int c0 = o0 + warp_n * 32 + ni * 8 + (L & 3) * 2;
                float2 qb = *(const float2*)(qbF + c0);
                float2 w0 = *(const float2*)(w0F + c0);
                float2 w1 = *(const float2*)(w1F + c0);
                float2 w2 = *(const float2*)(w2F + c0);
                float2 sw = *(const float2*)(swF + c0);
                float cva0 = w0.x * la0 + w1.x * la1 + w2.x * la2 + qb.x;
                float cva1 = w0.y * la0 + w1.y * la1 + w2.y * la2 + qb.y;
                float cvb0 = w0.x * lb0 + w1.x * lb1 + w2.x * lb2 + qb.x;
                float cvb1 = w0.y * lb0 + w1.y * lb1 + w2.y * lb2 + qb.y;
                scp[mi][0] += sw.x * ftanh(acc[mi][ni][0] + cva0)
                            + sw.y * ftanh(acc[mi][ni][1] + cva1);
                scp[mi][1] += sw.x * ftanh(acc[mi][ni][2] + cvb0)
                            + sw.y * ftanh(acc[mi][ni][3] + cvb1);
            }
        }
    }

    // partial score for 256 columns -> global accumulator
    #pragma unroll
    for (int mi = 0; mi < 2; mi++)
        #pragma unroll
        for (int h = 0; h < 2; h++) {
            float v = scp[mi][h];
            v += __shfl_xor_sync(0xffffffffu, v, 1);
            v += __shfl_xor_sync(0xffffffffu, v, 2);
            if ((L & 3) == 0) {
                int r = warp_m * 32 + mi * 16 + (L >> 2) + h * 8;
                atomicAdd(&g_scr[b * TT + t0 + r], v);
            }
        }
}

// ---------------- fused sigmoid + context -----------------------------------
// block (b, ts of 16): 128 t-values each; more blocks => more MLP in flight.
__global__ void __launch_bounds__(256)
k_ctx(const float* __restrict__ value, const float* __restrict__ s_b) {
    __shared__ float ps[128];
    int b = blockIdx.x, ts = blockIdx.y;
    int tix = threadIdx.x;
    int tbase = ts * 128;

    // sigmoid + write g_p + per-batch sum (first 4 warps)
    if (tix < 128) {
        int t = tbase + tix;
        float p = __fdividef(1.f, 1.f + __expf(-(g_scr[b * TT + t] + s_b[0])));
        g_p[b * TT + t] = p;
        ps[tix] = p;
        float ws = p;
        #pragma unroll
        for (int off = 16; off; off >>= 1)
            ws += __shfl_xor_sync(0xffffffffu, ws, off);
        if ((tix & 31) == 0) atomicAdd(&g_sum[b], ws);
    }
    __syncthreads();

    int h2 = tix;                               // float2 column index (0..255)
    const float2* vb = (const float2*)value + ((long)b * TT + tbase) * 256 + h2;
    float2 a0 = {0.f, 0.f}, a1 = {0.f, 0.f}, a2 = {0.f, 0.f}, a3 = {0.f, 0.f};
    float2 a4 = {0.f, 0.f}, a5 = {0.f, 0.f}, a6 = {0.f, 0.f}, a7 = {0.f, 0.f};
    #pragma unroll 2
    for (int t = 0; t < 128; t += 8) {
        float p0 = ps[t], p1 = ps[t+1], p2 = ps[t+2], p3 = ps[t+3];
        float p4 = ps[t+4], p5 = ps[t+5], p6 = ps[t+6], p7 = ps[t+7];
        float2 v0 = vb[(long)(t + 0) * 256];
        float2 v1 = vb[(long)(t + 1) * 256];
        float2 v2 = vb[(long)(t + 2) * 256];
        float2 v3 = vb[(long)(t + 3) * 256];
        float2 v4 = vb[(long)(t + 4) * 256];
        float2 v5 = vb[(long)(t + 5) * 256];
        float2 v6 = vb[(long)(t + 6) * 256];
        float2 v7 = vb[(long)(t + 7) * 256];
        a0.x += p0 * v0.x; a0.y += p0 * v0.y;
        a1.x += p1 * v1.x; a1.y += p1 * v1.y;
        a2.x += p2 * v2.x; a2.y += p2 * v2.y;
        a3.x += p3 * v3.x; a3.y += p3 * v3.y;
        a4.x += p4 * v4.x; a4.y += p4 * v4.y;
        a5.x += p5 * v5.x; a5.y += p5 * v5.y;
        a6.x += p6 * v6.x; a6.y += p6 * v6.y;
        a7.x += p7 * v7.x; a7.y += p7 * v7.y;
    }
    float rx = ((a0.x + a1.x) + (a2.x + a3.x)) + ((a4.x + a5.x) + (a6.x + a7.x));
    float ry = ((a0.y + a1.y) + (a2.y + a3.y)) + ((a4.y + a5.y) + (a6.y + a7.y));
    atomicAdd(&g_ctx[b * HH + 2 * h2 + 0], rx);
    atomicAdd(&g_ctx[b * HH + 2 * h2 + 1], ry);
}

__global__ void k_fin(float* __restrict__ out) {
    int i = blockIdx.x * 256 + threadIdx.x;
    if (i < BB * HH) out[i] = g_ctx[i] / g_sum[i / HH];
    if (i < BB * TT) out[BB * HH + i] = g_p[i] / g_sum[i / TT];
}

// ---------------------------------------------------------------------------
extern "C" void kernel_launch(void* const* d_in, const int* in_sizes, int n_in,
                              void* d_out, int out_size) {
    const float* query  = (const float*)d_in[0];
    const float* value  = (const float*)d_in[1];
    const float* la     = (const float*)d_in[2];
    const float* conv_w = (const float*)d_in[3];
    const float* conv_b = (const float*)d_in[4];
    const float* q_w    = (const float*)d_in[5];
    const float* v_w    = (const float*)d_in[6];
    const float* s_w    = (const float*)d_in[7];
    const float* s_b    = (const float*)d_in[8];
    const float* bias   = (const float*)d_in[9];
    float* out = (float*)d_out;

    cudaFuncSetAttribute(k_main, cudaFuncAttributeMaxDynamicSharedMemorySize,
                         SMEM_REQ);

    k_init<<<256, 256>>>(v_w);
    k_qproj<<<HH, 256>>>(query, q_w);
    k_main<<<dim3((TT / MT) * 2, BB), 256, SMEM_REQ>>>(value, la, conv_w,
                                                       conv_b, s_w, bias);
    k_ctx<<<dim3(BB, 16), 256>>>(value, s_b);
    k_fin<<<(BB * TT + 255) / 256, 256>>>(out);
}

// round 16
// speedup vs baseline: 1.3905x; 1.0080x over previous
#include <cuda_runtime.h>
#include <cuda_bf16.h>
#include <cuda_fp16.h>
#include <math.h>
#include <stdint.h>

#define BB 32
#define TT 2048
#define HH 512

#define MT  64                  // t-rows per CTA
#define KC  64                  // K-chunk
#define NOCH 2                  // N chunks of 128 per CTA (half of total)
#define NC  (NOCH * (HH / KC))  // 16 chunks per CTA

// ---------------- scratch (device globals; no allocation allowed) ----------
__device__ float g_q[BB * HH];
__device__ float g_p[BB * TT];
__device__ float g_scr[BB * TT];    // raw score accumulator (pre-sigmoid)
__device__ float g_ctx[BB * HH];
__device__ float g_sum[BB];
__device__ __half g_vwh[HH * HH];   // v_w in fp16
__device__ __half g_vh[BB * TT * HH];  // value in fp16 (64MB)

// ---------------- SMEM layout (byte offsets from 1024-aligned base) --------
// buffer: [A 8K fp16 64x64][B 16K fp16 128x64] ; rows 128B pitch, swizzled
#define OFF_A    0
#define OFF_B    8192
#define BUF_SZ   24576
#define OFF_QB   49152
#define OFF_W0   51200
#define OFF_W1   53248
#define OFF_W2   55296
#define OFF_SW   57344
#define OFF_LA   59392    // 66 floats
#define SMEM_END 59904
#define SMEM_REQ (SMEM_END + 1024)   // x2 CTAs well under 227KB

// ---------------- helpers ---------------------------------------------------
__device__ __forceinline__ uint32_t smem_u32(const void* p) {
    uint32_t a;
    asm("{ .reg .u64 t; cvta.to.shared.u64 t, %1; cvt.u32.u64 %0, t; }"
        : "=r"(a) : "l"(p));
    return a;
}
__device__ __forceinline__ uint64_t gaddr(const void* p) {
    uint64_t a;
    asm("cvta.to.global.u64 %0, %1;" : "=l"(a) : "l"(p));
    return a;
}
__device__ __forceinline__ void cpa16(uint32_t d, uint64_t s) {
    asm volatile("cp.async.cg.shared.global [%0], [%1], 16;"
                 :: "r"(d), "l"(s) : "memory");
}
#define CP_COMMIT() asm volatile("cp.async.commit_group;" ::: "memory")
#define CP_WAIT0()  asm volatile("cp.async.wait_group 0;" ::: "memory")

__device__ __forceinline__ void ldsm4(uint32_t* r, uint32_t a) {
    asm volatile("ldmatrix.sync.aligned.m8n8.x4.shared.b16 {%0,%1,%2,%3}, [%4];"
                 : "=r"(r[0]), "=r"(r[1]), "=r"(r[2]), "=r"(r[3]) : "r"(a));
}
__device__ __forceinline__ void mma_f16(float* d, const uint32_t* a,
                                        uint32_t b0, uint32_t b1) {
    asm volatile(
        "mma.sync.aligned.m16n8k16.row.col.f32.f16.f16.f32 "
        "{%0,%1,%2,%3},{%4,%5,%6,%7},{%8,%9},{%0,%1,%2,%3};"
        : "+f"(d[0]), "+f"(d[1]), "+f"(d[2]), "+f"(d[3])
        : "r"(a[0]), "r"(a[1]), "r"(a[2]), "r"(a[3]), "r"(b0), "r"(b1));
}
__device__ __forceinline__ float ftanh(float x) {
    float y;
    asm("tanh.approx.f32 %0, %1;" : "=f"(y) : "f"(x));
    return y;
}
__device__ __forceinline__ uint32_t pkh(float a, float b) {
    __half2 h = __floats2half2_rn(a, b);
    return *(uint32_t*)&h;
}

// ---------------- init: zero accumulators + convert v_w to fp16 -------------
__global__ void __launch_bounds__(256)
k_init(const float* __restrict__ v_w) {
    int i = blockIdx.x * 256 + threadIdx.x;        // 65536 threads
    if (i < BB * HH) g_ctx[i] = 0.f;
    if (i < BB)      g_sum[i] = 0.f;
    g_scr[i] = 0.f;                                // BB*TT == 65536
    float4 v = ((const float4*)v_w)[i];            // HH*HH/4 == 65536
    ((uint2*)g_vwh)[i] = make_uint2(pkh(v.x, v.y), pkh(v.z, v.w));
}

// value -> fp16 copy
__global__ void __launch_bounds__(256)
k_convh(const float* __restrict__ value) {
    long i4 = (long)blockIdx.x * 256 + threadIdx.x;   // 4 elems each
    float4 v = *((const float4*)value + i4);
    ((uint2*)g_vh)[i4] = make_uint2(pkh(v.x, v.y), pkh(v.z, v.w));
}

// q[b,o]: one block per o; warp w covers b in [4w, 4w+4)
__global__ void __launch_bounds__(256)
k_qproj(const float* __restrict__ query, const float* __restrict__ q_w) {
    int o = blockIdx.x, lane = threadIdx.x & 31, warp = threadIdx.x >> 5;
    const float* wrow = q_w + o * HH;
    float acc0 = 0.f, acc1 = 0.f, acc2 = 0.f, acc3 = 0.f;
    int b0 = warp * 4;
    for (int k = lane; k < HH; k += 32) {
        float w = __ldg(wrow + k);
        acc0 += w * __ldg(query + (b0 + 0) * HH + k);
        acc1 += w * __ldg(query + (b0 + 1) * HH + k);
        acc2 += w * __ldg(query + (b0 + 2) * HH + k);
        acc3 += w * __ldg(query + (b0 + 3) * HH + k);
    }
    #pragma unroll
    for (int off = 16; off; off >>= 1) {
        acc0 += __shfl_xor_sync(0xffffffffu, acc0, off);
        acc1 += __shfl_xor_sync(0xffffffffu, acc1, off);
        acc2 += __shfl_xor_sync(0xffffffffu, acc2, off);
        acc3 += __shfl_xor_sync(0xffffffffu, acc3, off);
    }
    if (lane == 0) {
        g_q[(b0 + 0) * HH + o] = acc0;
        g_q[(b0 + 1) * HH + o] = acc1;
        g_q[(b0 + 2) * HH + o] = acc2;
        g_q[(b0 + 3) * HH + o] = acc3;
    }
}

// ---------------- main fp16 HMMA kernel -------------------------------------
// CTA = (b, t-tile of 64, N-half of 256). grid (64, 32): x = t-tile*2 + nh.
__global__ void __launch_bounds__(256, 2)
k_main(const float* __restrict__ la,
       const float* __restrict__ conv_w, const float* __restrict__ conv_b,
       const float* __restrict__ s_w,    const float* __restrict__ bias)
{
    extern __shared__ char smraw[];
    uint32_t raw = smem_u32(smraw);
    uint32_t sb  = (raw + 1023) & ~1023u;
    char* base   = smraw + (sb - raw);

    int tid = threadIdx.x, L = tid & 31, wid = tid >> 5;
    int warp_m = wid >> 2, warp_n = wid & 3;      // 2 x 4
    int b  = blockIdx.y;
    int t0 = (blockIdx.x >> 1) * MT;
    int ochb = (blockIdx.x & 1) * NOCH;           // global o-chunk base (0 or 2)

    uint64_t vhG = gaddr(g_vh) + (uint64_t)(((long)b * TT + t0) * HH) * 2;
    uint64_t vwG = gaddr(g_vwh);

    // per chunk: A 64x8 units (512) + B 128x8 units (1024) = 1536; 6/thread
    auto issue_chunk = [&](int pc) {
        int och = ochb + (pc >> 3), kc = pc & 7;
        int kt = kc * KC, o0 = och * 128;
        uint32_t tb = sb + (uint32_t)(pc & 1) * BUF_SZ;
        #pragma unroll
        for (int i = 0; i < 6; i++) {
            int id = tid + i * 256;
            if (id < 512) {                // A fp16: row pitch 128B
                int r = id >> 3, c8 = id & 7;
                uint32_t so = (uint32_t)(r * 128 + ((c8 * 16) ^ ((r & 7) << 4)));
                uint64_t ga = (uint64_t)((long)r * HH + kt + c8 * 8) * 2;
                cpa16(tb + OFF_A + so, vhG + ga);
            } else {                       // B fp16: row pitch 128B
                int id2 = id - 512;
                int r = id2 >> 3, c8 = id2 & 7;
                uint32_t so = (uint32_t)(r * 128 + ((c8 * 16) ^ ((r & 7) << 4)));
                uint64_t gb = (uint64_t)((long)(o0 + r) * HH + kt + c8 * 8) * 2;
                cpa16(tb + OFF_B + so, vwG + gb);
            }
        }
    };

    issue_chunk(0);
    CP_COMMIT();

    float* qbF = (float*)(base + OFF_QB);
    float* w0F = (float*)(base + OFF_W0);
    float* w1F = (float*)(base + OFF_W1);
    float* w2F = (float*)(base + OFF_W2);
    float* swF = (float*)(base + OFF_SW);
    float* laF = (float*)(base + OFF_LA);
    for (int i = tid; i < HH; i += 256) {
        qbF[i] = g_q[b * HH + i] + bias[i] + conv_b[i];
        w0F[i] = conv_w[i * 3 + 0];
        w1F[i] = conv_w[i * 3 + 1];
        w2F[i] = conv_w[i * 3 + 2];
        swF[i] = s_w[i];
    }
    if (tid < MT + 2) {
        int gt = t0 - 1 + tid;
        laF[tid] = (gt >= 0 && gt < TT) ? la[b * TT + gt] : 0.f;
    }

    // each warp: 32 rows (2 x m16), 32 cols (4 x n8); fp16 rows 128B
    uint32_t aRow  = (uint32_t)(warp_m * 32 + (L & 15)) * 128;
    uint32_t bRow  = (uint32_t)(warp_n * 32 + (L & 7) + ((L >> 4) << 3)) * 128;
    uint32_t amask = (uint32_t)(L & 7) << 4;
    uint32_t aColK[4], bColK[4];
    #pragma unroll
    for (int kk = 0; kk < 4; kk++) {
        aColK[kk] = (uint32_t)(kk * 32 + ((L >> 4) << 4)) ^ amask;
        bColK[kk] = (uint32_t)(kk * 32 + (((L >> 3) & 1) << 4)) ^ amask;
    }

    float scp[2][2];
    scp[0][0] = scp[0][1] = scp[1][0] = scp[1][1] = 0.f;

    int pc = 0;
    for (int och = 0; och < NOCH; och++) {
        float acc[2][4][4];
        #pragma unroll
        for (int mi = 0; mi < 2; mi++)
            #pragma unroll
            for (int ni = 0; ni < 4; ni++)
                #pragma unroll
                for (int q = 0; q < 4; q++) acc[mi][ni][q] = 0.f;

        for (int kc = 0; kc < 8; kc++, pc++) {
            CP_WAIT0();
            __syncthreads();
            if (pc + 1 < NC) { issue_chunk(pc + 1); CP_COMMIT(); }

            uint32_t tb = sb + (uint32_t)(pc & 1) * BUF_SZ;
            uint32_t aB = tb + OFF_A + aRow;
            uint32_t bB = tb + OFF_B + bRow;

            #pragma unroll
            for (int kk = 0; kk < 4; kk++) {
                uint32_t ar[2][4], bh[4][2];
                ldsm4(ar[0], aB + aColK[kk]);
                ldsm4(ar[1], aB + 2048 + aColK[kk]);
                #pragma unroll
                for (int n2 = 0; n2 < 2; n2++) {
                    uint32_t rh[4];
                    ldsm4(rh, bB + (uint32_t)(n2 * 2048) + bColK[kk]);
                    bh[2*n2][0] = rh[0]; bh[2*n2][1] = rh[1];
                    bh[2*n2+1][0] = rh[2]; bh[2*n2+1][1] = rh[3];
                }
                #pragma unroll
                for (int mi = 0; mi < 2; mi++)
                    #pragma unroll
                    for (int ni = 0; ni < 4; ni++)
                        mma_f16(acc[mi][ni], ar[mi], bh[ni][0], bh[ni][1]);
            }
        }

        int o0 = (ochb + och) * 128;
        #pragma unroll
        for (int mi = 0; mi < 2; mi++) {
            int r0 = warp_m * 32 + mi * 16 + (L >> 2);
            float la0 = laF[r0],     la1 = laF[r0 + 1], la2 = laF[r0 + 2];
            float lb0 = laF[r0 + 8], lb1 = laF[r0 + 9], lb2 = laF[r0 + 10];
            #pragma unroll
            for (int ni = 0; ni < 4; ni++) {
                int c0 = o0 + warp_n * 32 + ni * 8 + (L & 3) * 2;
                float2 qb = *(const float2*)(qbF + c0);
                float2 w0 = *(const float2*)(w0F + c0);
                float2 w1 = *(const float2*)(w1F + c0);
                float2 w2 = *(const float2*)(w2F + c0);
                float2 sw = *(const float2*)(swF + c0);
                float cva0 = w0.x * la0 + w1.x * la1 + w2.x * la2 + qb.x;
                float cva1 = w0.y * la0 + w1.y * la1 + w2.y * la2 + qb.y;
                float cvb0 = w0.x * lb0 + w1.x * lb1 + w2.x * lb2 + qb.x;
                float cvb1 = w0.y * lb0 + w1.y * lb1 + w2.y * lb2 + qb.y;
                scp[mi][0] += sw.x * ftanh(acc[mi][ni][0] + cva0)
                            + sw.y * ftanh(acc[mi][ni][1] + cva1);
                scp[mi][1] += sw.x * ftanh(acc[mi][ni][2] + cvb0)
                            + sw.y * ftanh(acc[mi][ni][3] + cvb1);
            }
        }
    }

    // partial score for 256 columns -> global accumulator
    #pragma unroll
    for (int mi = 0; mi < 2; mi++)
        #pragma unroll
        for (int h = 0; h < 2; h++) {
            float v = scp[mi][h];
            v += __shfl_xor_sync(0xffffffffu, v, 1);
            v += __shfl_xor_sync(0xffffffffu, v, 2);
            if ((L & 3) == 0) {
                int r = warp_m * 32 + mi * 16 + (L >> 2) + h * 8;
                atomicAdd(&g_scr[b * TT + t0 + r], v);
            }
        }
}

// ---------------- fused sigmoid + context (fp16 value reads) ----------------
// block (b, ts of 16): 128 t-values each.
__global__ void __launch_bounds__(256)
k_ctx(const float* __restrict__ s_b) {
    __shared__ float ps[128];
    int b = blockIdx.x, ts = blockIdx.y;
    int tix = threadIdx.x;
    int tbase = ts * 128;

    if (tix < 128) {
        int t = tbase + tix;
        float p = __fdividef(1.f, 1.f + __expf(-(g_scr[b * TT + t] + s_b[0])));
        g_p[b * TT + t] = p;
        ps[tix] = p;
        float ws = p;
        #pragma unroll
        for (int off = 16; off; off >>= 1)
            ws += __shfl_xor_sync(0xffffffffu, ws, off);
        if ((tix & 31) == 0) atomicAdd(&g_sum[b], ws);
    }
    __syncthreads();

    // thread: uint4 column j (8 halves), t-stripe q (stride 4)
    int j = tix & 63, q = tix >> 6;
    const uint4* vh = (const uint4*)g_vh + ((long)b * TT + tbase) * 64 + j;
    float r8[8];
    #pragma unroll
    for (int e = 0; e < 8; e++) r8[e] = 0.f;

    #pragma unroll 4
    for (int i = 0; i < 32; i++) {
        int t = q + i * 4;
        float p = ps[t];
        uint4 v = vh[(long)t * 64];
        float2 f0 = __half22float2(*(const __half2*)&v.x);
        float2 f1 = __half22float2(*(const __half2*)&v.y);
        float2 f2 = __half22float2(*(const __half2*)&v.z);
        float2 f3 = __half22float2(*(const __half2*)&v.w);
        r8[0] += p * f0.x; r8[1] += p * f0.y;
        r8[2] += p * f1.x; r8[3] += p * f1.y;
        r8[4] += p * f2.x; r8[5] += p * f2.y;
        r8[6] += p * f3.x; r8[7] += p * f3.y;
    }
    #pragma unroll
    for (int e = 0; e < 8; e++)
        atomicAdd(&g_ctx[b * HH + j * 8 + e], r8[e]);
}

__global__ void k_fin(float* __restrict__ out) {
    int i = blockIdx.x * 256 + threadIdx.x;
    if (i < BB * HH) out[i] = g_ctx[i] / g_sum[i / HH];
    if (i < BB * TT) out[BB * HH + i] = g_p[i] / g_sum[i / TT];
}

// ---------------------------------------------------------------------------
extern "C" void kernel_launch(void* const* d_in, const int* in_sizes, int n_in,
                              void* d_out, int out_size) {
    const float* query  = (const float*)d_in[0];
    const float* value  = (const float*)d_in[1];
    const float* la     = (const float*)d_in[2];
    const float* conv_w = (const float*)d_in[3];
    const float* conv_b = (const float*)d_in[4];
    const float* q_w    = (const float*)d_in[5];
    const float* v_w    = (const float*)d_in[6];
    const float* s_w    = (const float*)d_in[7];
    const float* s_b    = (const float*)d_in[8];
    const float* bias   = (const float*)d_in[9];
    float* out = (float*)d_out;

    cudaFuncSetAttribute(k_main, cudaFuncAttributeMaxDynamicSharedMemorySize,
                         SMEM_REQ);

    k_init<<<256, 256>>>(v_w);
    k_convh<<<(BB * TT * HH / 4) / 256, 256>>>(value);
    k_qproj<<<HH, 256>>>(query, q_w);
    k_main<<<dim3((TT / MT) * 2, BB), 256, SMEM_REQ>>>(la, conv_w, conv_b,
                                                       s_w, bias);
    k_ctx<<<dim3(BB, 16), 256>>>(s_b);
    k_fin<<<(BB * TT + 255) / 256, 256>>>(out);
}

// round 17
// speedup vs baseline: 1.9070x; 1.3715x over previous
#include <cuda_runtime.h>
#include <cuda_bf16.h>
#include <cuda_fp16.h>
#include <math.h>
#include <stdint.h>

#define BB 32
#define TT 2048
#define HH 512

#define MT  64                  // t-rows per CTA
#define KC  64                  // K-chunk
#define NOCH 2                  // N chunks of 128 per CTA (half of total)
#define NC  (NOCH * (HH / KC))  // 16 chunks per CTA

// ---------------- scratch (device globals; no allocation allowed) ----------
__device__ float g_q[BB * HH];
__device__ float g_p[BB * TT];
__device__ float g_scr[BB * TT];    // raw score accumulator (pre-sigmoid)
__device__ float g_ctx[BB * HH];
__device__ float g_sum[BB];
__device__ __half g_vwh[HH * HH];   // v_w in fp16
__device__ __half g_vh[BB * TT * HH];  // value in fp16 (64MB)

// ---------------- SMEM layout (byte offsets from 1024-aligned base) --------
// 3 buffers: [A 8K fp16 64x64][B 16K fp16 128x64] each; rows 128B, swizzled
#define OFF_A    0
#define OFF_B    8192
#define BUF_SZ   24576
#define OFF_QB   73728
#define OFF_W0   75776
#define OFF_W1   77824
#define OFF_W2   79872
#define OFF_SW   81920
#define OFF_LA   83968    // 66 floats
#define SMEM_END 84480
#define SMEM_REQ (SMEM_END + 1024)   // x2 CTAs = ~171KB <= 227KB

// ---------------- helpers ---------------------------------------------------
__device__ __forceinline__ uint32_t smem_u32(const void* p) {
    uint32_t a;
    asm("{ .reg .u64 t; cvta.to.shared.u64 t, %1; cvt.u32.u64 %0, t; }"
        : "=r"(a) : "l"(p));
    return a;
}
__device__ __forceinline__ uint64_t gaddr(const void* p) {
    uint64_t a;
    asm("cvta.to.global.u64 %0, %1;" : "=l"(a) : "l"(p));
    return a;
}
__device__ __forceinline__ void cpa16(uint32_t d, uint64_t s) {
    asm volatile("cp.async.cg.shared.global [%0], [%1], 16;"
                 :: "r"(d), "l"(s) : "memory");
}
#define CP_COMMIT() asm volatile("cp.async.commit_group;" ::: "memory")
#define CP_WAIT0()  asm volatile("cp.async.wait_group 0;" ::: "memory")
#define CP_WAIT1()  asm volatile("cp.async.wait_group 1;" ::: "memory")

__device__ __forceinline__ void ldsm4(uint32_t* r, uint32_t a) {
    asm volatile("ldmatrix.sync.aligned.m8n8.x4.shared.b16 {%0,%1,%2,%3}, [%4];"
                 : "=r"(r[0]), "=r"(r[1]), "=r"(r[2]), "=r"(r[3]) : "r"(a));
}
__device__ __forceinline__ void mma_f16(float* d, const uint32_t* a,
                                        uint32_t b0, uint32_t b1) {
    asm volatile(
        "mma.sync.aligned.m16n8k16.row.col.f32.f16.f16.f32 "
        "{%0,%1,%2,%3},{%4,%5,%6,%7},{%8,%9},{%0,%1,%2,%3};"
        : "+f"(d[0]), "+f"(d[1]), "+f"(d[2]), "+f"(d[3])
        : "r"(a[0]), "r"(a[1]), "r"(a[2]), "r"(a[3]), "r"(b0), "r"(b1));
}
__device__ __forceinline__ float ftanh(float x) {
    float y;
    asm("tanh.approx.f32 %0, %1;" : "=f"(y) : "f"(x));
    return y;
}
__device__ __forceinline__ uint32_t pkh(float a, float b) {
    __half2 h = __floats2half2_rn(a, b);
    return *(uint32_t*)&h;
}

// ---------------- value -> fp16 copy + zero accumulators + v_w fp16 ---------
__global__ void __launch_bounds__(256)
k_convh(const float* __restrict__ value, const float* __restrict__ v_w) {
    long i4 = (long)blockIdx.x * 256 + threadIdx.x;   // 4 elems each
    float4 v = *((const float4*)value + i4);
    ((uint2*)g_vh)[i4] = make_uint2(pkh(v.x, v.y), pkh(v.z, v.w));
    if (i4 < 65536) {
        int i = (int)i4;
        if (i < BB * HH) g_ctx[i] = 0.f;
        if (i < BB)      g_sum[i] = 0.f;
        g_scr[i] = 0.f;                            // BB*TT == 65536
        float4 w = ((const float4*)v_w)[i];        // HH*HH/4 == 65536
        ((uint2*)g_vwh)[i] = make_uint2(pkh(w.x, w.y), pkh(w.z, w.w));
    }
}

// q[b,o]: one block per o; warp w covers b in [4w, 4w+4)
__global__ void __launch_bounds__(256)
k_qproj(const float* __restrict__ query, const float* __restrict__ q_w) {
    int o = blockIdx.x, lane = threadIdx.x & 31, warp = threadIdx.x >> 5;
    const float* wrow = q_w + o * HH;
    float acc0 = 0.f, acc1 = 0.f, acc2 = 0.f, acc3 = 0.f;
    int b0 = warp * 4;
    for (int k = lane; k < HH; k += 32) {
        float w = __ldg(wrow + k);
        acc0 += w * __ldg(query + (b0 + 0) * HH + k);
        acc1 += w * __ldg(query + (b0 + 1) * HH + k);
        acc2 += w * __ldg(query + (b0 + 2) * HH + k);
        acc3 += w * __ldg(query + (b0 + 3) * HH + k);
    }
    #pragma unroll
    for (int off = 16; off; off >>= 1) {
        acc0 += __shfl_xor_sync(0xffffffffu, acc0, off);
        acc1 += __shfl_xor_sync(0xffffffffu, acc1, off);
        acc2 += __shfl_xor_sync(0xffffffffu, acc2, off);
        acc3 += __shfl_xor_sync(0xffffffffu, acc3, off);
    }
    if (lane == 0) {
        g_q[(b0 + 0) * HH + o] = acc0;
        g_q[(b0 + 1) * HH + o] = acc1;
        g_q[(b0 + 2) * HH + o] = acc2;
        g_q[(b0 + 3) * HH + o] = acc3;
    }
}

// ---------------- main fp16 HMMA kernel (3-stage pipeline) -------------------
// CTA = (b, t-tile of 64, N-half of 256). grid (64, 32): x = t-tile*2 + nh.
__global__ void __launch_bounds__(256, 2)
k_main(const float* __restrict__ la,
       const float* __restrict__ conv_w, const float* __restrict__ conv_b,
       const float* __restrict__ s_w,    const float* __restrict__ bias)
{
    extern __shared__ char smraw[];
    uint32_t raw = smem_u32(smraw);
    uint32_t sb  = (raw + 1023) & ~1023u;
    char* base   = smraw + (sb - raw);

    int tid = threadIdx.x, L = tid & 31, wid = tid >> 5;
    int warp_m = wid >> 2, warp_n = wid & 3;      // 2 x 4
    int b  = blockIdx.y;
    int t0 = (blockIdx.x >> 1) * MT;
    int ochb = (blockIdx.x & 1) * NOCH;           // global o-chunk base (0 or 2)

    uint64_t vhG = gaddr(g_vh) + (uint64_t)(((long)b * TT + t0) * HH) * 2;
    uint64_t vwG = gaddr(g_vwh);

    // per chunk: A 64x8 units (512) + B 128x8 units (1024) = 1536; 6/thread
    auto issue_chunk = [&](int pc) {
        int och = ochb + (pc >> 3), kc = pc & 7;
        int kt = kc * KC, o0 = och * 128;
        uint32_t tb = sb + (uint32_t)(pc % 3) * BUF_SZ;
        #pragma unroll
        for (int i = 0; i < 6; i++) {
            int id = tid + i * 256;
            if (id < 512) {                // A fp16: row pitch 128B
                int r = id >> 3, c8 = id & 7;
                uint32_t so = (uint32_t)(r * 128 + ((c8 * 16) ^ ((r & 7) << 4)));
                uint64_t ga = (uint64_t)((long)r * HH + kt + c8 * 8) * 2;
                cpa16(tb + OFF_A + so, vhG + ga);
            } else {                       // B fp16: row pitch 128B
                int id2 = id - 512;
                int r = id2 >> 3, c8 = id2 & 7;
                uint32_t so = (uint32_t)(r * 128 + ((c8 * 16) ^ ((r & 7) << 4)));
                uint64_t gb = (uint64_t)((long)(o0 + r) * HH + kt + c8 * 8) * 2;
                cpa16(tb + OFF_B + so, vwG + gb);
            }
        }
    };

    issue_chunk(0);
    CP_COMMIT();
    issue_chunk(1);
    CP_COMMIT();

    float* qbF = (float*)(base + OFF_QB);
    float* w0F = (float*)(base + OFF_W0);
    float* w1F = (float*)(base + OFF_W1);
    float* w2F = (float*)(base + OFF_W2);
    float* swF = (float*)(base + OFF_SW);
    float* laF = (float*)(base + OFF_LA);
    for (int i = tid; i < HH; i += 256) {
        qbF[i] = g_q[b * HH + i] + bias[i] + conv_b[i];
        w0F[i] = conv_w[i * 3 + 0];
        w1F[i] = conv_w[i * 3 + 1];
        w2F[i] = conv_w[i * 3 + 2];
        swF[i] = s_w[i];
    }
    if (tid < MT + 2) {
        int gt = t0 - 1 + tid;
        laF[tid] = (gt >= 0 && gt < TT) ? la[b * TT + gt] : 0.f;
    }

    // each warp: 32 rows (2 x m16), 32 cols (4 x n8); fp16 rows 128B
    uint32_t aRow  = (uint32_t)(warp_m * 32 + (L & 15)) * 128;
    uint32_t bRow  = (uint32_t)(warp_n * 32 + (L & 7) + ((L >> 4) << 3)) * 128;
    uint32_t amask = (uint32_t)(L & 7) << 4;
    uint32_t aColK[4], bColK[4];
    #pragma unroll
    for (int kk = 0; kk < 4; kk++) {
        aColK[kk] = (uint32_t)(kk * 32 + ((L >> 4) << 4)) ^ amask;
        bColK[kk] = (uint32_t)(kk * 32 + (((L >> 3) & 1) << 4)) ^ amask;
    }

    float scp[2][2];
    scp[0][0] = scp[0][1] = scp[1][0] = scp[1][1] = 0.f;

    int pc = 0;
    for (int och = 0; och < NOCH; och++) {
        float acc[2][4][4];
        #pragma unroll
        for (int mi = 0; mi < 2; mi++)
            #pragma unroll
            for (int ni = 0; ni < 4; ni++)
                #pragma unroll
                for (int q = 0; q < 4; q++) acc[mi][ni][q] = 0.f;

        for (int kc = 0; kc < 8; kc++, pc++) {
            // 3-stage: need chunk pc resident; pc+1 may still be in flight
            if (pc + 2 < NC) CP_WAIT1();
            else             CP_WAIT0();
            __syncthreads();
            if (pc + 2 < NC) { issue_chunk(pc + 2); CP_COMMIT(); }

            uint32_t tb = sb + (uint32_t)(pc % 3) * BUF_SZ;
            uint32_t aB = tb + OFF_A + aRow;
            uint32_t bB = tb + OFF_B + bRow;

            #pragma unroll
            for (int kk = 0; kk < 4; kk++) {
                uint32_t ar[2][4], bh[4][2];
                ldsm4(ar[0], aB + aColK[kk]);
                ldsm4(ar[1], aB + 2048 + aColK[kk]);
                #pragma unroll
                for (int n2 = 0; n2 < 2; n2++) {
                    uint32_t rh[4];
                    ldsm4(rh, bB + (uint32_t)(n2 * 2048) + bColK[kk]);
                    bh[2*n2][0] = rh[0]; bh[2*n2][1] = rh[1];
                    bh[2*n2+1][0] = rh[2]; bh[2*n2+1][1] = rh[3];
                }
                #pragma unroll
                for (int mi = 0; mi < 2; mi++)
                    #pragma unroll
                    for (int ni = 0; ni < 4; ni++)
                        mma_f16(acc[mi][ni], ar[mi], bh[ni][0], bh[ni][1]);
            }
        }

        int o0 = (ochb + och) * 128;
        #pragma unroll
        for (int mi = 0; mi < 2; mi++) {
            int r0 = warp_m * 32 + mi * 16 + (L >> 2);
            float la0 = laF[r0],     la1 = laF[r0 + 1], la2 = laF[r0 + 2];
            float lb0 = laF[r0 + 8], lb1 = laF[r0 + 9], lb2 = laF[r0 + 10];
            #pragma unroll
            for (int ni = 0; ni < 4; ni++) {
                int c0 = o0 + warp_n * 32 + ni * 8 + (L & 3) * 2;
                float2 qb = *(const float2*)(qbF + c0);
                float2 w0 = *(const float2*)(w0F + c0);
                float2 w1 = *(const float2*)(w1F + c0);
                float2 w2 = *(const float2*)(w2F + c0);
                float2 sw = *(const float2*)(swF + c0);
                float cva0 = w0.x * la0 + w1.x * la1 + w2.x * la2 + qb.x;
                float cva1 = w0.y * la0 + w1.y * la1 + w2.y * la2 + qb.y;
                float cvb0 = w0.x * lb0 + w1.x * lb1 + w2.x * lb2 + qb.x;
                float cvb1 = w0.y * lb0 + w1.y * lb1 + w2.y * lb2 + qb.y;
                scp[mi][0] += sw.x * ftanh(acc[mi][ni][0] + cva0)
                            + sw.y * ftanh(acc[mi][ni][1] + cva1);
                scp[mi][1] += sw.x * ftanh(acc[mi][ni][2] + cvb0)
                            + sw.y * ftanh(acc[mi][ni][3] + cvb1);
            }
        }
    }

    // partial score for 256 columns -> global accumulator
    #pragma unroll
    for (int mi = 0; mi < 2; mi++)
        #pragma unroll
        for (int h = 0; h < 2; h++) {
            float v = scp[mi][h];
            v += __shfl_xor_sync(0xffffffffu, v, 1);
            v += __shfl_xor_sync(0xffffffffu, v, 2);
            if ((L & 3) == 0) {
                int r = warp_m * 32 + mi * 16 + (L >> 2) + h * 8;
                atomicAdd(&g_scr[b * TT + t0 + r], v);
            }
        }
}

// ---------------- fused sigmoid + context (fp16 value reads) ----------------
// block (b, ts of 16): 128 t-values each.
__global__ void __launch_bounds__(256)
k_ctx(const float* __restrict__ s_b) {
    __shared__ float ps[128];
    int b = blockIdx.x, ts = blockIdx.y;
    int tix = threadIdx.x;
    int tbase = ts * 128;

    if (tix < 128) {
        int t = tbase + tix;
        float p = __fdividef(1.f, 1.f + __expf(-(g_scr[b * TT + t] + s_b[0])));
        g_p[b * TT + t] = p;
        ps[tix] = p;
        float ws = p;
        #pragma unroll
        for (int off = 16; off; off >>= 1)
            ws += __shfl_xor_sync(0xffffffffu, ws, off);
        if ((tix & 31) == 0) atomicAdd(&g_sum[b], ws);
    }
    __syncthreads();

    // thread: uint4 column j (8 halves), t-stripe q (stride 4)
    int j = tix & 63, q = tix >> 6;
    const uint4* vh = (const uint4*)g_vh + ((long)b * TT + tbase) * 64 + j;
    float r8[8];
    #pragma unroll
    for (int e = 0; e < 8; e++) r8[e] = 0.f;

    #pragma unroll 4
    for (int i = 0; i < 32; i++) {
        int t = q + i * 4;
        float p = ps[t];
        uint4 v = vh[(long)t * 64];
        float2 f0 = __half22float2(*(const __half2*)&v.x);
        float2 f1 = __half22float2(*(const __half2*)&v.y);
        float2 f2 = __half22float2(*(const __half2*)&v.z);
        float2 f3 = __half22float2(*(const __half2*)&v.w);
        r8[0] += p * f0.x; r8[1] += p * f0.y;
        r8[2] += p * f1.x; r8[3] += p * f1.y;
        r8[4] += p * f2.x; r8[5] += p * f2.y;
        r8[6] += p * f3.x; r8[7] += p * f3.y;
    }
    #pragma unroll
    for (int e = 0; e < 8; e++)
        atomicAdd(&g_ctx[b * HH + j * 8 + e], r8[e]);
}

__global__ void k_fin(float* __restrict__ out) {
    int i = blockIdx.x * 256 + threadIdx.x;
    if (i < BB * HH) out[i] = g_ctx[i] / g_sum[i / HH];
    if (i < BB * TT) out[BB * HH + i] = g_p[i] / g_sum[i / TT];
}

// ---------------------------------------------------------------------------
extern "C" void kernel_launch(void* const* d_in, const int* in_sizes, int n_in,
                              void* d_out, int out_size) {
    const float* query  = (const float*)d_in[0];
    const float* value  = (const float*)d_in[1];
    const float* la     = (const float*)d_in[2];
    const float* conv_w = (const float*)d_in[3];
    const float* conv_b = (const float*)d_in[4];
    const float* q_w    = (const float*)d_in[5];
    const float* v_w    = (const float*)d_in[6];
    const float* s_w    = (const float*)d_in[7];
    const float* s_b    = (const float*)d_in[8];
    const float* bias   = (const float*)d_in[9];
    float* out = (float*)d_out;

    cudaFuncSetAttribute(k_main, cudaFuncAttributeMaxDynamicSharedMemorySize,
                         SMEM_REQ);

    k_convh<<<(BB * TT * HH / 4) / 256, 256>>>(value, v_w);
    k_qproj<<<HH, 256>>>(query, q_w);
    k_main<<<dim3((TT / MT) * 2, BB), 256, SMEM_REQ>>>(la, conv_w, conv_b,
                                                       s_w, bias);
    k_ctx<<<dim3(BB, 16), 256>>>(s_b);
    k_fin<<<(BB * TT + 255) / 256, 256>>>(out);
}